// round 1
// baseline (speedup 1.0000x reference)
#include <cuda_runtime.h>
#include <cuda_bf16.h>
#include <math.h>

// Problem constants
#define LQ   2048          // target length
#define SK   2048          // memory length
#define NB   4             // batch (heads dim N in [L,N,E])
#define EE   1024          // embed dim
#define FFD  4096          // feed-forward dim
#define MTOK (LQ * NB)     // 8192 token rows

// ---------------------------------------------------------------------------
// Scratch (device globals; allocation-free per harness rules)
// ---------------------------------------------------------------------------
__device__ float g_h [(long long)MTOK * EE];       // LN output
__device__ float g_q [(long long)MTOK * EE];
__device__ float g_k [(long long)MTOK * EE];
__device__ float g_v [(long long)MTOK * EE];
__device__ float g_s [(long long)NB * LQ * SK];    // scores / probs
__device__ float g_a [(long long)MTOK * EE];       // attn out (pre out-proj)
__device__ float g_ff[(long long)MTOK * FFD];      // MLP hidden

// ---------------------------------------------------------------------------
// Reductions
// ---------------------------------------------------------------------------
__device__ __forceinline__ float warpSum(float v) {
#pragma unroll
    for (int o = 16; o > 0; o >>= 1) v += __shfl_xor_sync(0xffffffffu, v, o);
    return v;
}
__device__ __forceinline__ float warpMax(float v) {
#pragma unroll
    for (int o = 16; o > 0; o >>= 1) v = fmaxf(v, __shfl_xor_sync(0xffffffffu, v, o));
    return v;
}
// 256-thread block reductions; result broadcast to all threads.
__device__ __forceinline__ float blockSum(float v, float* sh) {
    int lane = threadIdx.x & 31, wid = threadIdx.x >> 5;
    v = warpSum(v);
    if (lane == 0) sh[wid] = v;
    __syncthreads();
    float r = (lane < 8) ? sh[lane] : 0.f;
    r = warpSum(r);
    __syncthreads();
    return r;
}
__device__ __forceinline__ float blockMax(float v, float* sh) {
    int lane = threadIdx.x & 31, wid = threadIdx.x >> 5;
    v = warpMax(v);
    if (lane == 0) sh[wid] = v;
    __syncthreads();
    float r = (lane < 8) ? sh[lane] : -3.4e38f;
    r = warpMax(r);
    __syncthreads();
    return r;
}

// ---------------------------------------------------------------------------
// LayerNorm: one block (256 thr) per row of E=1024
// ---------------------------------------------------------------------------
__global__ void ln_kernel(const float* __restrict__ x, const float* __restrict__ g,
                          const float* __restrict__ b, float* __restrict__ out) {
    __shared__ float sh[32];
    long long row = blockIdx.x;
    const float4* xr = (const float4*)(x + row * EE);
    float4 v = xr[threadIdx.x];
    float s  = v.x + v.y + v.z + v.w;
    float sq = v.x * v.x + v.y * v.y + v.z * v.z + v.w * v.w;
    s  = blockSum(s,  sh);
    sq = blockSum(sq, sh);
    float mean = s * (1.f / EE);
    float var  = sq * (1.f / EE) - mean * mean;
    float inv  = rsqrtf(var + 1e-5f);
    float4 gv = ((const float4*)g)[threadIdx.x];
    float4 bv = ((const float4*)b)[threadIdx.x];
    float4 o;
    o.x = (v.x - mean) * inv * gv.x + bv.x;
    o.y = (v.y - mean) * inv * gv.y + bv.y;
    o.z = (v.z - mean) * inv * gv.z + bv.z;
    o.w = (v.w - mean) * inv * gv.w + bv.w;
    ((float4*)(out + row * EE))[threadIdx.x] = o;
}

// ---------------------------------------------------------------------------
// Softmax over S=2048; one block (256 thr) per row; row-resident in regs.
// row = n*LQ + l; optional additive mask[l, :].
// ---------------------------------------------------------------------------
__global__ void softmax_kernel(float* __restrict__ s, const float* __restrict__ mask) {
    __shared__ float sh[32];
    long long row = blockIdx.x;
    int l = (int)(row & (LQ - 1));
    float4* sr = (float4*)(s + row * (long long)SK);
    float4 va = sr[threadIdx.x];
    float4 vb = sr[threadIdx.x + 256];
    if (mask) {
        const float4* mr = (const float4*)(mask + (long long)l * SK);
        float4 ma = mr[threadIdx.x], mb = mr[threadIdx.x + 256];
        va.x += ma.x; va.y += ma.y; va.z += ma.z; va.w += ma.w;
        vb.x += mb.x; vb.y += mb.y; vb.z += mb.z; vb.w += mb.w;
    }
    float mx = fmaxf(fmaxf(fmaxf(va.x, va.y), fmaxf(va.z, va.w)),
                     fmaxf(fmaxf(vb.x, vb.y), fmaxf(vb.z, vb.w)));
    mx = blockMax(mx, sh);
    va.x = __expf(va.x - mx); va.y = __expf(va.y - mx);
    va.z = __expf(va.z - mx); va.w = __expf(va.w - mx);
    vb.x = __expf(vb.x - mx); vb.y = __expf(vb.y - mx);
    vb.z = __expf(vb.z - mx); vb.w = __expf(vb.w - mx);
    float sum = va.x + va.y + va.z + va.w + vb.x + vb.y + vb.z + vb.w;
    sum = blockSum(sum, sh);
    float inv = 1.f / sum;
    va.x *= inv; va.y *= inv; va.z *= inv; va.w *= inv;
    vb.x *= inv; vb.y *= inv; vb.z *= inv; vb.w *= inv;
    sr[threadIdx.x] = va;
    sr[threadIdx.x + 256] = vb;
}

// ---------------------------------------------------------------------------
// GEMM: C = epi( A @ op(B) ), 128x128 tile, BK=8, 256 threads, 8x8 microtile.
// TRANSB=true : B is [N,K] row-major (C=A@B^T)  — all weight matmuls, QK^T
// TRANSB=false: B is [K,N] row-major (C=A@B)    — P@V
// Epilogue: v = (acc + bias[col]) * alpha ; ACT==1 -> QuickGELU ; += res.
// All of M, N divisible by 128 and K by 8. Batched via blockIdx.z + strides.
// ---------------------------------------------------------------------------
template <bool TRANSB, int ACT>
__global__ void __launch_bounds__(256, 2)
gemm_kernel(const float* __restrict__ A, const float* __restrict__ B,
            const float* __restrict__ bias, const float* res, float* C,
            int K, int lda, int ldb, int ldc,
            long long sA, long long sB, long long sC, float alpha) {
    A += (long long)blockIdx.z * sA;
    B += (long long)blockIdx.z * sB;
    C += (long long)blockIdx.z * sC;
    if (res) res += (long long)blockIdx.z * sC;

    const int bm = blockIdx.y * 128;
    const int bn = blockIdx.x * 128;
    __shared__ float As[8][128];
    __shared__ float Bs[8][128];
    const int tid = threadIdx.x;
    const int a_m = tid >> 1;            // 0..127
    const int a_k = (tid & 1) << 2;      // 0 or 4
    const int b_k = tid >> 5;            // 0..7  (NN load)
    const int b_n = (tid & 31) << 2;     // 0..124
    const int tx  = (tid & 15) << 3;     // col offset
    const int ty  = (tid >> 4) << 3;     // row offset

    float acc[8][8];
#pragma unroll
    for (int i = 0; i < 8; i++)
#pragma unroll
        for (int j = 0; j < 8; j++) acc[i][j] = 0.f;

    const float* Aptr  = A + (long long)(bm + a_m) * lda + a_k;
    const float* BptrT = B + (long long)(bn + a_m) * ldb + a_k;
    const float* BptrN = B + (long long)b_k * ldb + bn + b_n;

    for (int k0 = 0; k0 < K; k0 += 8) {
        float4 av = *(const float4*)(Aptr + k0);
        As[a_k + 0][a_m] = av.x; As[a_k + 1][a_m] = av.y;
        As[a_k + 2][a_m] = av.z; As[a_k + 3][a_m] = av.w;
        if (TRANSB) {
            float4 bv = *(const float4*)(BptrT + k0);
            Bs[a_k + 0][a_m] = bv.x; Bs[a_k + 1][a_m] = bv.y;
            Bs[a_k + 2][a_m] = bv.z; Bs[a_k + 3][a_m] = bv.w;
        } else {
            float4 bv = *(const float4*)(BptrN + (long long)k0 * ldb);
            *(float4*)&Bs[b_k][b_n] = bv;
        }
        __syncthreads();
#pragma unroll
        for (int kk = 0; kk < 8; kk++) {
            float ar[8], br[8];
            *(float4*)(ar)     = *(float4*)&As[kk][ty];
            *(float4*)(ar + 4) = *(float4*)&As[kk][ty + 4];
            *(float4*)(br)     = *(float4*)&Bs[kk][tx];
            *(float4*)(br + 4) = *(float4*)&Bs[kk][tx + 4];
#pragma unroll
            for (int i = 0; i < 8; i++)
#pragma unroll
                for (int j = 0; j < 8; j++)
                    acc[i][j] = fmaf(ar[i], br[j], acc[i][j]);
        }
        __syncthreads();
    }

#pragma unroll
    for (int i = 0; i < 8; i++) {
        long long row = bm + ty + i;
#pragma unroll
        for (int j = 0; j < 8; j++) {
            int col = bn + tx + j;
            float v = acc[i][j];
            if (bias) v += bias[col];
            v *= alpha;
            if (ACT == 1) v = v / (1.f + __expf(-1.702f * v));  // QuickGELU
            if (res) v += res[row * ldc + col];
            C[row * ldc + col] = v;
        }
    }
}

// ---------------------------------------------------------------------------
// Host launcher
// ---------------------------------------------------------------------------
extern "C" void kernel_launch(void* const* d_in, const int* in_sizes, int n_in,
                              void* d_out, int out_size) {
    const float* tgt    = (const float*)d_in[0];
    const float* memory = (const float*)d_in[1];
    const float* mask   = (const float*)d_in[2];
    const float* sa_qw  = (const float*)d_in[3];
    const float* sa_kw  = (const float*)d_in[4];
    const float* sa_vw  = (const float*)d_in[5];
    const float* sa_b   = (const float*)d_in[6];
    const float* sa_ow  = (const float*)d_in[7];
    const float* sa_ob  = (const float*)d_in[8];
    const float* ca_qw  = (const float*)d_in[9];
    const float* ca_kw  = (const float*)d_in[10];
    const float* ca_vw  = (const float*)d_in[11];
    const float* ca_b   = (const float*)d_in[12];
    const float* ca_ow  = (const float*)d_in[13];
    const float* ca_ob  = (const float*)d_in[14];
    const float* ln1_g  = (const float*)d_in[15];
    const float* ln1_b  = (const float*)d_in[16];
    const float* ln2_g  = (const float*)d_in[17];
    const float* ln2_b  = (const float*)d_in[18];
    const float* ln3_g  = (const float*)d_in[19];
    const float* ln3_b  = (const float*)d_in[20];
    const float* w1     = (const float*)d_in[21];
    const float* b1     = (const float*)d_in[22];
    const float* w2     = (const float*)d_in[23];
    const float* b2     = (const float*)d_in[24];
    float* x = (float*)d_out;

    float *hb, *qb, *kb, *vb, *sb, *ab, *ffb;
    cudaGetSymbolAddress((void**)&hb,  g_h);
    cudaGetSymbolAddress((void**)&qb,  g_q);
    cudaGetSymbolAddress((void**)&kb,  g_k);
    cudaGetSymbolAddress((void**)&vb,  g_v);
    cudaGetSymbolAddress((void**)&sb,  g_s);
    cudaGetSymbolAddress((void**)&ab,  g_a);
    cudaGetSymbolAddress((void**)&ffb, g_ff);

    const float scale = 1.0f / 32.0f;  // 1024^-0.5
    const long long SBATCH = (long long)LQ * SK;

    // x = tgt
    cudaMemcpyAsync(x, tgt, (size_t)MTOK * EE * sizeof(float),
                    cudaMemcpyDeviceToDevice, 0);

    dim3 gProj(EE / 128, MTOK / 128);      // (8, 64)
    dim3 gScore(SK / 128, LQ / 128, NB);   // (16, 16, 4)
    dim3 gPV(EE / 128, LQ / 128, NB);      // (8, 16, 4)
    dim3 gFF1(FFD / 128, MTOK / 128);      // (32, 64)

    // ---------------- self-attention ----------------
    ln_kernel<<<MTOK, 256>>>(x, ln1_g, ln1_b, hb);
    gemm_kernel<true, 0><<<gProj, 256>>>(hb, sa_qw, sa_b,          nullptr, qb,
                                         EE, EE, EE, EE, 0, 0, 0, scale);
    gemm_kernel<true, 0><<<gProj, 256>>>(hb, sa_kw, sa_b + EE,     nullptr, kb,
                                         EE, EE, EE, EE, 0, 0, 0, 1.f);
    gemm_kernel<true, 0><<<gProj, 256>>>(hb, sa_vw, sa_b + 2 * EE, nullptr, vb,
                                         EE, EE, EE, EE, 0, 0, 0, 1.f);
    // scores[n] = q_n @ k_n^T   (rows strided by NB*EE)
    gemm_kernel<true, 0><<<gScore, 256>>>(qb, kb, nullptr, nullptr, sb,
                                          EE, NB * EE, NB * EE, SK,
                                          EE, EE, SBATCH, 1.f);
    softmax_kernel<<<NB * LQ, 256>>>(sb, mask);
    // attn[n] = P_n @ v_n
    gemm_kernel<false, 0><<<gPV, 256>>>(sb, vb, nullptr, nullptr, ab,
                                        SK, SK, NB * EE, NB * EE,
                                        SBATCH, EE, EE, 1.f);
    // x = x + attn @ ow^T + ob
    gemm_kernel<true, 0><<<gProj, 256>>>(ab, sa_ow, sa_ob, x, x,
                                         EE, EE, EE, EE, 0, 0, 0, 1.f);

    // ---------------- cross-attention ----------------
    ln_kernel<<<MTOK, 256>>>(x, ln2_g, ln2_b, hb);
    gemm_kernel<true, 0><<<gProj, 256>>>(hb,     ca_qw, ca_b,          nullptr, qb,
                                         EE, EE, EE, EE, 0, 0, 0, scale);
    gemm_kernel<true, 0><<<gProj, 256>>>(memory, ca_kw, ca_b + EE,     nullptr, kb,
                                         EE, EE, EE, EE, 0, 0, 0, 1.f);
    gemm_kernel<true, 0><<<gProj, 256>>>(memory, ca_vw, ca_b + 2 * EE, nullptr, vb,
                                         EE, EE, EE, EE, 0, 0, 0, 1.f);
    gemm_kernel<true, 0><<<gScore, 256>>>(qb, kb, nullptr, nullptr, sb,
                                          EE, NB * EE, NB * EE, SK,
                                          EE, EE, SBATCH, 1.f);
    softmax_kernel<<<NB * LQ, 256>>>(sb, nullptr);
    gemm_kernel<false, 0><<<gPV, 256>>>(sb, vb, nullptr, nullptr, ab,
                                        SK, SK, NB * EE, NB * EE,
                                        SBATCH, EE, EE, 1.f);
    gemm_kernel<true, 0><<<gProj, 256>>>(ab, ca_ow, ca_ob, x, x,
                                         EE, EE, EE, EE, 0, 0, 0, 1.f);

    // ---------------- MLP ----------------
    ln_kernel<<<MTOK, 256>>>(x, ln3_g, ln3_b, hb);
    gemm_kernel<true, 1><<<gFF1, 256>>>(hb, w1, b1, nullptr, ffb,
                                        EE, EE, EE, FFD, 0, 0, 0, 1.f);
    gemm_kernel<true, 0><<<gProj, 256>>>(ffb, w2, b2, x, x,
                                         FFD, FFD, FFD, EE, 0, 0, 0, 1.f);
}

// round 2
// speedup vs baseline: 3.9525x; 3.9525x over previous
#include <cuda_runtime.h>
#include <cuda_bf16.h>
#include <math.h>
#include <stdint.h>

#define LQ   2048
#define SK   2048
#define NB   4
#define EE   1024
#define FFD  4096
#define MTOK (LQ * NB)

typedef __nv_bfloat16  bf16;
typedef __nv_bfloat162 bf162;

// ---------------------------------------------------------------------------
// Scratch (device globals)
// ---------------------------------------------------------------------------
__device__ bf16 s_hh [(size_t)MTOK * EE],  s_hl [(size_t)MTOK * EE];
__device__ bf16 s_qh [(size_t)MTOK * EE],  s_ql [(size_t)MTOK * EE];
__device__ bf16 s_kh [(size_t)MTOK * EE],  s_kl [(size_t)MTOK * EE];
__device__ bf16 s_vh [(size_t)MTOK * EE],  s_vl [(size_t)MTOK * EE];
__device__ bf16 s_ph [(size_t)NB * LQ * SK], s_pl [(size_t)NB * LQ * SK];
__device__ bf16 s_abh[(size_t)MTOK * EE],  s_abl[(size_t)MTOK * EE];
__device__ bf16 s_ffh[(size_t)MTOK * FFD], s_ffl[(size_t)MTOK * FFD];
__device__ bf16 s_wh [(size_t)FFD * EE],   s_wl [(size_t)FFD * EE];
__device__ bf16 s_mh [(size_t)MTOK * EE],  s_ml [(size_t)MTOK * EE];
__device__ float g_s [(size_t)NB * LQ * SK];

// ---------------------------------------------------------------------------
// Small helpers
// ---------------------------------------------------------------------------
__device__ __forceinline__ void split2(float v, bf16& h, bf16& l) {
    h = __float2bfloat16_rn(v);
    l = __float2bfloat16_rn(v - __bfloat162float(h));
}

__device__ __forceinline__ float warpSum(float v) {
#pragma unroll
    for (int o = 16; o > 0; o >>= 1) v += __shfl_xor_sync(0xffffffffu, v, o);
    return v;
}
__device__ __forceinline__ float warpMax(float v) {
#pragma unroll
    for (int o = 16; o > 0; o >>= 1) v = fmaxf(v, __shfl_xor_sync(0xffffffffu, v, o));
    return v;
}
__device__ __forceinline__ float blockSum(float v, float* sh) {
    int lane = threadIdx.x & 31, wid = threadIdx.x >> 5;
    v = warpSum(v);
    if (lane == 0) sh[wid] = v;
    __syncthreads();
    float r = (lane < 8) ? sh[lane] : 0.f;
    r = warpSum(r);
    __syncthreads();
    return r;
}
__device__ __forceinline__ float blockMax(float v, float* sh) {
    int lane = threadIdx.x & 31, wid = threadIdx.x >> 5;
    v = warpMax(v);
    if (lane == 0) sh[wid] = v;
    __syncthreads();
    float r = (lane < 8) ? sh[lane] : -3.4e38f;
    r = warpMax(r);
    __syncthreads();
    return r;
}

// ---------------------------------------------------------------------------
// PTX wrappers
// ---------------------------------------------------------------------------
__device__ __forceinline__ void cpa16(uint32_t dst, const void* src) {
    asm volatile("cp.async.cg.shared.global [%0], [%1], 16;" :: "r"(dst), "l"(src));
}
#define CP_COMMIT() asm volatile("cp.async.commit_group;" ::: "memory")
#define CP_WAIT0()  asm volatile("cp.async.wait_group 0;" ::: "memory")
#define CP_WAIT1()  asm volatile("cp.async.wait_group 1;" ::: "memory")

__device__ __forceinline__ void ldsm4(uint32_t* r, uint32_t addr) {
    asm volatile("ldmatrix.sync.aligned.m8n8.x4.shared.b16 {%0,%1,%2,%3}, [%4];"
        : "=r"(r[0]), "=r"(r[1]), "=r"(r[2]), "=r"(r[3]) : "r"(addr));
}
__device__ __forceinline__ void ldsm2(uint32_t* r, uint32_t addr) {
    asm volatile("ldmatrix.sync.aligned.m8n8.x2.shared.b16 {%0,%1}, [%2];"
        : "=r"(r[0]), "=r"(r[1]) : "r"(addr));
}
__device__ __forceinline__ void ldsm2t(uint32_t* r, uint32_t addr) {
    asm volatile("ldmatrix.sync.aligned.m8n8.x2.trans.shared.b16 {%0,%1}, [%2];"
        : "=r"(r[0]), "=r"(r[1]) : "r"(addr));
}
__device__ __forceinline__ void mma_bf16(float* d, const uint32_t* a, const uint32_t* b) {
    asm volatile(
        "mma.sync.aligned.m16n8k16.row.col.f32.bf16.bf16.f32 "
        "{%0,%1,%2,%3}, {%4,%5,%6,%7}, {%8,%9}, {%0,%1,%2,%3};\n"
        : "+f"(d[0]), "+f"(d[1]), "+f"(d[2]), "+f"(d[3])
        : "r"(a[0]), "r"(a[1]), "r"(a[2]), "r"(a[3]), "r"(b[0]), "r"(b[1]));
}

// ---------------------------------------------------------------------------
// Elementwise f32 -> bf16 hi/lo split (weights / memory)
// ---------------------------------------------------------------------------
__global__ void cvt_split_kernel(const float* __restrict__ x,
                                 bf16* __restrict__ hi, bf16* __restrict__ lo,
                                 long long n4) {
    long long i = blockIdx.x * (long long)blockDim.x + threadIdx.x;
    if (i >= n4) return;
    float4 v = ((const float4*)x)[i];
    bf16 h0, l0, h1, l1, h2, l2, h3, l3;
    split2(v.x, h0, l0); split2(v.y, h1, l1);
    split2(v.z, h2, l2); split2(v.w, h3, l3);
    ((bf162*)hi)[i * 2]     = bf162(h0, h1);
    ((bf162*)hi)[i * 2 + 1] = bf162(h2, h3);
    ((bf162*)lo)[i * 2]     = bf162(l0, l1);
    ((bf162*)lo)[i * 2 + 1] = bf162(l2, l3);
}

// ---------------------------------------------------------------------------
// LayerNorm -> split bf16 output. One block (256 thr) per row of E=1024.
// ---------------------------------------------------------------------------
__global__ void ln_kernel(const float* __restrict__ x, const float* __restrict__ g,
                          const float* __restrict__ b,
                          bf16* __restrict__ oh, bf16* __restrict__ ol) {
    __shared__ float sh[32];
    long long row = blockIdx.x;
    float4 v = ((const float4*)(x + row * EE))[threadIdx.x];
    float s  = v.x + v.y + v.z + v.w;
    float sq = v.x * v.x + v.y * v.y + v.z * v.z + v.w * v.w;
    s  = blockSum(s,  sh);
    sq = blockSum(sq, sh);
    float mean = s * (1.f / EE);
    float var  = sq * (1.f / EE) - mean * mean;
    float inv  = rsqrtf(var + 1e-5f);
    float4 gv = ((const float4*)g)[threadIdx.x];
    float4 bv = ((const float4*)b)[threadIdx.x];
    float o0 = (v.x - mean) * inv * gv.x + bv.x;
    float o1 = (v.y - mean) * inv * gv.y + bv.y;
    float o2 = (v.z - mean) * inv * gv.z + bv.z;
    float o3 = (v.w - mean) * inv * gv.w + bv.w;
    bf16 h0, l0, h1, l1, h2, l2, h3, l3;
    split2(o0, h0, l0); split2(o1, h1, l1);
    split2(o2, h2, l2); split2(o3, h3, l3);
    bf162* ph = (bf162*)(oh + row * EE);
    bf162* pl = (bf162*)(ol + row * EE);
    ph[threadIdx.x * 2]     = bf162(h0, h1);
    ph[threadIdx.x * 2 + 1] = bf162(h2, h3);
    pl[threadIdx.x * 2]     = bf162(l0, l1);
    pl[threadIdx.x * 2 + 1] = bf162(l2, l3);
}

// ---------------------------------------------------------------------------
// Softmax over S=2048 -> split bf16 probs. One block (256 thr) per row.
// ---------------------------------------------------------------------------
__global__ void softmax_kernel(const float* __restrict__ s, const float* __restrict__ mask,
                               bf16* __restrict__ oh, bf16* __restrict__ ol) {
    __shared__ float sh[32];
    long long row = blockIdx.x;
    int l = (int)(row & (LQ - 1));
    const float4* sr = (const float4*)(s + row * (long long)SK);
    float4 va = sr[threadIdx.x];
    float4 vb = sr[threadIdx.x + 256];
    if (mask) {
        const float4* mr = (const float4*)(mask + (long long)l * SK);
        float4 ma = mr[threadIdx.x], mb = mr[threadIdx.x + 256];
        va.x += ma.x; va.y += ma.y; va.z += ma.z; va.w += ma.w;
        vb.x += mb.x; vb.y += mb.y; vb.z += mb.z; vb.w += mb.w;
    }
    float mx = fmaxf(fmaxf(fmaxf(va.x, va.y), fmaxf(va.z, va.w)),
                     fmaxf(fmaxf(vb.x, vb.y), fmaxf(vb.z, vb.w)));
    mx = blockMax(mx, sh);
    va.x = __expf(va.x - mx); va.y = __expf(va.y - mx);
    va.z = __expf(va.z - mx); va.w = __expf(va.w - mx);
    vb.x = __expf(vb.x - mx); vb.y = __expf(vb.y - mx);
    vb.z = __expf(vb.z - mx); vb.w = __expf(vb.w - mx);
    float sum = va.x + va.y + va.z + va.w + vb.x + vb.y + vb.z + vb.w;
    sum = blockSum(sum, sh);
    float inv = 1.f / sum;
    bf162* ph = (bf162*)(oh + row * (long long)SK);
    bf162* pl = (bf162*)(ol + row * (long long)SK);
    bf16 h0, l0, h1, l1, h2, l2, h3, l3;
    split2(va.x * inv, h0, l0); split2(va.y * inv, h1, l1);
    split2(va.z * inv, h2, l2); split2(va.w * inv, h3, l3);
    ph[threadIdx.x * 2]     = bf162(h0, h1);
    ph[threadIdx.x * 2 + 1] = bf162(h2, h3);
    pl[threadIdx.x * 2]     = bf162(l0, l1);
    pl[threadIdx.x * 2 + 1] = bf162(l2, l3);
    split2(vb.x * inv, h0, l0); split2(vb.y * inv, h1, l1);
    split2(vb.z * inv, h2, l2); split2(vb.w * inv, h3, l3);
    ph[(threadIdx.x + 256) * 2]     = bf162(h0, h1);
    ph[(threadIdx.x + 256) * 2 + 1] = bf162(h2, h3);
    pl[(threadIdx.x + 256) * 2]     = bf162(l0, l1);
    pl[(threadIdx.x + 256) * 2 + 1] = bf162(l2, l3);
}

// ---------------------------------------------------------------------------
// Tensor-core GEMM with 2-term bf16 split: C = epi(A @ op(B)).
// 128x128 CTA tile, BK=32, 256 threads (8 warps in 2x4), 64x32 warp tile.
// TRANSB: B stored [N,K] row-major (K-major). !TRANSB: B stored [K,N].
// SPLIT_OUT=1: write Ch/Cl bf16 hi/lo.  SPLIT_OUT=0: write f32 C (+res).
// Epilogue: v=(acc+bias)*alpha; ACT==1 -> QuickGELU.
// Dynamic smem: 2 stages x (A hi/lo + B hi/lo) = 81920 bytes.
// ---------------------------------------------------------------------------
#define SMEM_STAGE_B 40960u
#define A_LO_OFF     10240u
#define B_HI_OFF     20480u

template <bool TRANSB, int ACT, int SPLIT_OUT>
__global__ void __launch_bounds__(256, 1)
gemm_tc(const bf16* __restrict__ Ah, const bf16* __restrict__ Al,
        const bf16* __restrict__ Bh, const bf16* __restrict__ Bl,
        const float* __restrict__ bias, const float* __restrict__ res,
        float* C, bf16* Ch, bf16* Cl,
        int K, int lda, int ldb, int ldc,
        long long sA, long long sB, long long sC, float alpha) {
    Ah += (long long)blockIdx.z * sA;  Al += (long long)blockIdx.z * sA;
    Bh += (long long)blockIdx.z * sB;  Bl += (long long)blockIdx.z * sB;
    if (SPLIT_OUT) { Ch += (long long)blockIdx.z * sC; Cl += (long long)blockIdx.z * sC; }
    else           { C  += (long long)blockIdx.z * sC; if (res) res += (long long)blockIdx.z * sC; }

    extern __shared__ bf16 smem[];
    const uint32_t sbase = (uint32_t)__cvta_generic_to_shared(smem);
    const int tid  = threadIdx.x;
    const int lane = tid & 31;
    const int warp = tid >> 5;
    const int wm = warp >> 2;   // 0..1
    const int wn = warp & 3;    // 0..3
    const int bm = blockIdx.y * 128;
    const int bn = blockIdx.x * 128;

    float acc[4][4][4];
#pragma unroll
    for (int i = 0; i < 4; i++)
#pragma unroll
        for (int j = 0; j < 4; j++)
#pragma unroll
            for (int q = 0; q < 4; q++) acc[i][j][q] = 0.f;

    auto load_stage = [&](int st, int k0) {
        uint32_t sb = sbase + (uint32_t)st * SMEM_STAGE_B;
#pragma unroll
        for (int i = 0; i < 2; i++) {
            int c = tid + i * 256;
            int row = c >> 2, kc = c & 3;
            size_t off = (size_t)(bm + row) * lda + k0 + kc * 8;
            uint32_t d = sb + row * 80 + kc * 16;
            cpa16(d, Ah + off);
            cpa16(d + A_LO_OFF, Al + off);
        }
        if (TRANSB) {
#pragma unroll
            for (int i = 0; i < 2; i++) {
                int c = tid + i * 256;
                int row = c >> 2, kc = c & 3;
                size_t off = (size_t)(bn + row) * ldb + k0 + kc * 8;
                uint32_t d = sb + B_HI_OFF + row * 80 + kc * 16;
                cpa16(d, Bh + off);
                cpa16(d + A_LO_OFF, Bl + off);
            }
        } else {
#pragma unroll
            for (int i = 0; i < 2; i++) {
                int c = tid + i * 256;
                int row = c >> 4, nc = c & 15;   // row: 0..31 (k), nc: 0..15
                size_t off = (size_t)(k0 + row) * ldb + bn + nc * 8;
                uint32_t d = sb + B_HI_OFF + row * 272 + nc * 16;
                cpa16(d, Bh + off);
                cpa16(d + A_LO_OFF, Bl + off);
            }
        }
        CP_COMMIT();
    };

    auto compute_stage = [&](int st) {
        uint32_t sA_ = sbase + (uint32_t)st * SMEM_STAGE_B;
        uint32_t sB_ = sA_ + B_HI_OFF;
#pragma unroll
        for (int ks = 0; ks < 2; ks++) {
            const int k16 = ks * 16;
            uint32_t ah[4][4], al[4][4], bh[4][2], bl[4][2];
            const int arow = lane & 15;
            const int acol = k16 + (lane >> 4) * 8;
#pragma unroll
            for (int mt = 0; mt < 4; mt++) {
                uint32_t addr = sA_ + (uint32_t)((wm * 64 + mt * 16 + arow) * 80 + acol * 2);
                ldsm4(ah[mt], addr);
                ldsm4(al[mt], addr + A_LO_OFF);
            }
            if (TRANSB) {
                const int brow = lane & 7;
                const int bk   = k16 + ((lane >> 3) & 1) * 8;
#pragma unroll
                for (int nt = 0; nt < 4; nt++) {
                    uint32_t addr = sB_ + (uint32_t)((wn * 32 + nt * 8 + brow) * 80 + bk * 2);
                    ldsm2(bh[nt], addr);
                    ldsm2(bl[nt], addr + A_LO_OFF);
                }
            } else {
                const int brow = k16 + (lane & 15);
#pragma unroll
                for (int nt = 0; nt < 4; nt++) {
                    uint32_t addr = sB_ + (uint32_t)(brow * 272 + (wn * 32 + nt * 8) * 2);
                    ldsm2t(bh[nt], addr);
                    ldsm2t(bl[nt], addr + A_LO_OFF);
                }
            }
#pragma unroll
            for (int mt = 0; mt < 4; mt++)
#pragma unroll
                for (int nt = 0; nt < 4; nt++) {
                    mma_bf16(acc[mt][nt], ah[mt], bh[nt]);
                    mma_bf16(acc[mt][nt], ah[mt], bl[nt]);
                    mma_bf16(acc[mt][nt], al[mt], bh[nt]);
                }
        }
    };

    const int KT = K >> 5;   // K / 32
    load_stage(0, 0);
    for (int kt = 0; kt < KT; kt++) {
        if (kt + 1 < KT) { load_stage((kt + 1) & 1, (kt + 1) * 32); CP_WAIT1(); }
        else             { CP_WAIT0(); }
        __syncthreads();
        compute_stage(kt & 1);
        __syncthreads();
    }

    // Epilogue
#pragma unroll
    for (int mt = 0; mt < 4; mt++) {
        const int r0 = bm + wm * 64 + mt * 16 + (lane >> 2);
#pragma unroll
        for (int nt = 0; nt < 4; nt++) {
            const int c = bn + wn * 32 + nt * 8 + (lane & 3) * 2;
            float bc0 = 0.f, bc1 = 0.f;
            if (bias) { bc0 = bias[c]; bc1 = bias[c + 1]; }
#pragma unroll
            for (int h = 0; h < 2; h++) {
                float v0 = acc[mt][nt][h * 2 + 0] + bc0;
                float v1 = acc[mt][nt][h * 2 + 1] + bc1;
                v0 *= alpha; v1 *= alpha;
                if (ACT == 1) {
                    v0 = v0 / (1.f + __expf(-1.702f * v0));
                    v1 = v1 / (1.f + __expf(-1.702f * v1));
                }
                const size_t row = (size_t)(r0 + h * 8);
                if (SPLIT_OUT) {
                    bf16 h0, l0, h1, l1;
                    split2(v0, h0, l0); split2(v1, h1, l1);
                    *(bf162*)(Ch + row * ldc + c) = bf162(h0, h1);
                    *(bf162*)(Cl + row * ldc + c) = bf162(l0, l1);
                } else {
                    if (res) {
                        const float2 rv = *(const float2*)(res + row * ldc + c);
                        v0 += rv.x; v1 += rv.y;
                    }
                    *(float2*)(C + row * ldc + c) = make_float2(v0, v1);
                }
            }
        }
    }
}

// ---------------------------------------------------------------------------
// Host launcher
// ---------------------------------------------------------------------------
extern "C" void kernel_launch(void* const* d_in, const int* in_sizes, int n_in,
                              void* d_out, int out_size) {
    const float* tgt    = (const float*)d_in[0];
    const float* memory = (const float*)d_in[1];
    const float* mask   = (const float*)d_in[2];
    const float* sa_qw  = (const float*)d_in[3];
    const float* sa_kw  = (const float*)d_in[4];
    const float* sa_vw  = (const float*)d_in[5];
    const float* sa_b   = (const float*)d_in[6];
    const float* sa_ow  = (const float*)d_in[7];
    const float* sa_ob  = (const float*)d_in[8];
    const float* ca_qw  = (const float*)d_in[9];
    const float* ca_kw  = (const float*)d_in[10];
    const float* ca_vw  = (const float*)d_in[11];
    const float* ca_b   = (const float*)d_in[12];
    const float* ca_ow  = (const float*)d_in[13];
    const float* ca_ob  = (const float*)d_in[14];
    const float* ln1_g  = (const float*)d_in[15];
    const float* ln1_b  = (const float*)d_in[16];
    const float* ln2_g  = (const float*)d_in[17];
    const float* ln2_b  = (const float*)d_in[18];
    const float* ln3_g  = (const float*)d_in[19];
    const float* ln3_b  = (const float*)d_in[20];
    const float* w1     = (const float*)d_in[21];
    const float* b1     = (const float*)d_in[22];
    const float* w2     = (const float*)d_in[23];
    const float* b2     = (const float*)d_in[24];
    float* x = (float*)d_out;

    bf16 *hh, *hl, *qh, *ql, *kh, *kl, *vh, *vl, *ph, *pl, *abh, *abl,
         *ffh, *ffl, *wh, *wl, *mh, *ml;
    float* sb;
    cudaGetSymbolAddress((void**)&hh,  s_hh);  cudaGetSymbolAddress((void**)&hl,  s_hl);
    cudaGetSymbolAddress((void**)&qh,  s_qh);  cudaGetSymbolAddress((void**)&ql,  s_ql);
    cudaGetSymbolAddress((void**)&kh,  s_kh);  cudaGetSymbolAddress((void**)&kl,  s_kl);
    cudaGetSymbolAddress((void**)&vh,  s_vh);  cudaGetSymbolAddress((void**)&vl,  s_vl);
    cudaGetSymbolAddress((void**)&ph,  s_ph);  cudaGetSymbolAddress((void**)&pl,  s_pl);
    cudaGetSymbolAddress((void**)&abh, s_abh); cudaGetSymbolAddress((void**)&abl, s_abl);
    cudaGetSymbolAddress((void**)&ffh, s_ffh); cudaGetSymbolAddress((void**)&ffl, s_ffl);
    cudaGetSymbolAddress((void**)&wh,  s_wh);  cudaGetSymbolAddress((void**)&wl,  s_wl);
    cudaGetSymbolAddress((void**)&mh,  s_mh);  cudaGetSymbolAddress((void**)&ml,  s_ml);
    cudaGetSymbolAddress((void**)&sb,  g_s);

    const int SMEM = 81920;
    cudaFuncSetAttribute((const void*)gemm_tc<true,  0, 1>, cudaFuncAttributeMaxDynamicSharedMemorySize, SMEM);
    cudaFuncSetAttribute((const void*)gemm_tc<true,  0, 0>, cudaFuncAttributeMaxDynamicSharedMemorySize, SMEM);
    cudaFuncSetAttribute((const void*)gemm_tc<false, 0, 1>, cudaFuncAttributeMaxDynamicSharedMemorySize, SMEM);
    cudaFuncSetAttribute((const void*)gemm_tc<true,  1, 1>, cudaFuncAttributeMaxDynamicSharedMemorySize, SMEM);

    const float scale = 1.0f / 32.0f;
    const long long SBATCH = (long long)LQ * SK;

    cudaMemcpyAsync(x, tgt, (size_t)MTOK * EE * sizeof(float),
                    cudaMemcpyDeviceToDevice, 0);

    dim3 gProj(EE / 128, MTOK / 128);       // (8, 64)
    dim3 gScore(SK / 128, LQ / 128, NB);    // (16, 16, 4)
    dim3 gPV(EE / 128, LQ / 128, NB);       // (8, 16, 4)
    dim3 gFF1(FFD / 128, MTOK / 128);       // (32, 64)

    const long long nW1 = (long long)EE * EE / 4;       // float4 count, 1M weights
    const long long nFF = (long long)FFD * EE / 4;      // 4M weights
    const long long nM  = (long long)MTOK * EE / 4;     // memory

#define CVT(src, dh, dl, n4) cvt_split_kernel<<<(unsigned)((n4) / 256), 256>>>(src, dh, dl, n4)

    // ---------------- self-attention ----------------
    ln_kernel<<<MTOK, 256>>>(x, ln1_g, ln1_b, hh, hl);
    CVT(sa_qw, wh, wl, nW1);
    gemm_tc<true, 0, 1><<<gProj, 256, SMEM>>>(hh, hl, wh, wl, sa_b, nullptr,
        nullptr, qh, ql, EE, EE, EE, EE, 0, 0, 0, scale);
    CVT(sa_kw, wh, wl, nW1);
    gemm_tc<true, 0, 1><<<gProj, 256, SMEM>>>(hh, hl, wh, wl, sa_b + EE, nullptr,
        nullptr, kh, kl, EE, EE, EE, EE, 0, 0, 0, 1.f);
    CVT(sa_vw, wh, wl, nW1);
    gemm_tc<true, 0, 1><<<gProj, 256, SMEM>>>(hh, hl, wh, wl, sa_b + 2 * EE, nullptr,
        nullptr, vh, vl, EE, EE, EE, EE, 0, 0, 0, 1.f);
    gemm_tc<true, 0, 0><<<gScore, 256, SMEM>>>(qh, ql, kh, kl, nullptr, nullptr,
        sb, nullptr, nullptr, EE, NB * EE, NB * EE, SK, EE, EE, SBATCH, 1.f);
    softmax_kernel<<<NB * LQ, 256>>>(sb, mask, ph, pl);
    gemm_tc<false, 0, 1><<<gPV, 256, SMEM>>>(ph, pl, vh, vl, nullptr, nullptr,
        nullptr, abh, abl, SK, SK, NB * EE, NB * EE, SBATCH, EE, EE, 1.f);
    CVT(sa_ow, wh, wl, nW1);
    gemm_tc<true, 0, 0><<<gProj, 256, SMEM>>>(abh, abl, wh, wl, sa_ob, x,
        x, nullptr, nullptr, EE, EE, EE, EE, 0, 0, 0, 1.f);

    // ---------------- cross-attention ----------------
    ln_kernel<<<MTOK, 256>>>(x, ln2_g, ln2_b, hh, hl);
    CVT(memory, mh, ml, nM);
    CVT(ca_qw, wh, wl, nW1);
    gemm_tc<true, 0, 1><<<gProj, 256, SMEM>>>(hh, hl, wh, wl, ca_b, nullptr,
        nullptr, qh, ql, EE, EE, EE, EE, 0, 0, 0, scale);
    CVT(ca_kw, wh, wl, nW1);
    gemm_tc<true, 0, 1><<<gProj, 256, SMEM>>>(mh, ml, wh, wl, ca_b + EE, nullptr,
        nullptr, kh, kl, EE, EE, EE, EE, 0, 0, 0, 1.f);
    CVT(ca_vw, wh, wl, nW1);
    gemm_tc<true, 0, 1><<<gProj, 256, SMEM>>>(mh, ml, wh, wl, ca_b + 2 * EE, nullptr,
        nullptr, vh, vl, EE, EE, EE, EE, 0, 0, 0, 1.f);
    gemm_tc<true, 0, 0><<<gScore, 256, SMEM>>>(qh, ql, kh, kl, nullptr, nullptr,
        sb, nullptr, nullptr, EE, NB * EE, NB * EE, SK, EE, EE, SBATCH, 1.f);
    softmax_kernel<<<NB * LQ, 256>>>(sb, nullptr, ph, pl);
    gemm_tc<false, 0, 1><<<gPV, 256, SMEM>>>(ph, pl, vh, vl, nullptr, nullptr,
        nullptr, abh, abl, SK, SK, NB * EE, NB * EE, SBATCH, EE, EE, 1.f);
    CVT(ca_ow, wh, wl, nW1);
    gemm_tc<true, 0, 0><<<gProj, 256, SMEM>>>(abh, abl, wh, wl, ca_ob, x,
        x, nullptr, nullptr, EE, EE, EE, EE, 0, 0, 0, 1.f);

    // ---------------- MLP ----------------
    ln_kernel<<<MTOK, 256>>>(x, ln3_g, ln3_b, hh, hl);
    CVT(w1, wh, wl, nFF);
    gemm_tc<true, 1, 1><<<gFF1, 256, SMEM>>>(hh, hl, wh, wl, b1, nullptr,
        nullptr, ffh, ffl, EE, EE, EE, FFD, 0, 0, 0, 1.f);
    CVT(w2, wh, wl, nFF);
    gemm_tc<true, 0, 0><<<gProj, 256, SMEM>>>(ffh, ffl, wh, wl, b2, x,
        x, nullptr, nullptr, FFD, FFD, FFD, EE, 0, 0, 0, 1.f);
#undef CVT
}

// round 5
// speedup vs baseline: 6.5412x; 1.6550x over previous
#include <cuda_runtime.h>
#include <cuda_fp16.h>
#include <math.h>
#include <stdint.h>

#define LQ   2048
#define SK   2048
#define NB   4
#define EE   1024
#define FFD  4096
#define MTOK (LQ * NB)

typedef __half  f16;
typedef __half2 f162;

// ---------------------------------------------------------------------------
// Scratch (device globals). A-side tensors: hi only. B-side (k, v, weights): hi+lo.
// ---------------------------------------------------------------------------
__device__ f16 s_hh [(size_t)MTOK * EE];                          // LN out (A only)
__device__ f16 s_qh [(size_t)MTOK * EE];                          // q (A only)
__device__ f16 s_kh [(size_t)MTOK * EE],  s_kl [(size_t)MTOK * EE];
__device__ f16 s_vh [(size_t)MTOK * EE],  s_vl [(size_t)MTOK * EE];
__device__ f16 s_ph [(size_t)NB * LQ * SK];                       // probs (A only)
__device__ f16 s_abh[(size_t)MTOK * EE];                          // attn out (A only)
__device__ f16 s_ffh[(size_t)MTOK * FFD];                         // MLP hidden (A only)
__device__ f16 s_wh [(size_t)FFD * EE],   s_wl [(size_t)FFD * EE];
__device__ f16 s_mh [(size_t)MTOK * EE];                          // memory (A only)
__device__ float g_s [(size_t)NB * LQ * SK];                      // f32 scores

// ---------------------------------------------------------------------------
// Helpers
// ---------------------------------------------------------------------------
__device__ __forceinline__ void split2h(float v, f16& h, f16& l) {
    h = __float2half_rn(v);
    l = __float2half_rn(v - __half2float(h));
}
__device__ __forceinline__ float warpSum(float v) {
#pragma unroll
    for (int o = 16; o > 0; o >>= 1) v += __shfl_xor_sync(0xffffffffu, v, o);
    return v;
}
__device__ __forceinline__ float warpMax(float v) {
#pragma unroll
    for (int o = 16; o > 0; o >>= 1) v = fmaxf(v, __shfl_xor_sync(0xffffffffu, v, o));
    return v;
}
__device__ __forceinline__ float blockSum(float v, float* sh) {
    int lane = threadIdx.x & 31, wid = threadIdx.x >> 5;
    v = warpSum(v);
    if (lane == 0) sh[wid] = v;
    __syncthreads();
    float r = (lane < 8) ? sh[lane] : 0.f;
    r = warpSum(r);
    __syncthreads();
    return r;
}
__device__ __forceinline__ float blockMax(float v, float* sh) {
    int lane = threadIdx.x & 31, wid = threadIdx.x >> 5;
    v = warpMax(v);
    if (lane == 0) sh[wid] = v;
    __syncthreads();
    float r = (lane < 8) ? sh[lane] : -3.4e38f;
    r = warpMax(r);
    __syncthreads();
    return r;
}

// ---------------------------------------------------------------------------
// PTX wrappers (baseline sm_80+ features only — compute_103-safe)
// ---------------------------------------------------------------------------
__device__ __forceinline__ void cpa16(uint32_t dst, const void* src) {
    asm volatile("cp.async.cg.shared.global [%0], [%1], 16;" :: "r"(dst), "l"(src));
}
#define CP_COMMIT() asm volatile("cp.async.commit_group;" ::: "memory")
#define CP_WAIT0()  asm volatile("cp.async.wait_group 0;" ::: "memory")
#define CP_WAIT1()  asm volatile("cp.async.wait_group 1;" ::: "memory")

__device__ __forceinline__ void ldsm4(uint32_t* r, uint32_t addr) {
    asm volatile("ldmatrix.sync.aligned.m8n8.x4.shared.b16 {%0,%1,%2,%3}, [%4];"
        : "=r"(r[0]), "=r"(r[1]), "=r"(r[2]), "=r"(r[3]) : "r"(addr));
}
__device__ __forceinline__ void ldsm2(uint32_t* r, uint32_t addr) {
    asm volatile("ldmatrix.sync.aligned.m8n8.x2.shared.b16 {%0,%1}, [%2];"
        : "=r"(r[0]), "=r"(r[1]) : "r"(addr));
}
__device__ __forceinline__ void ldsm2t(uint32_t* r, uint32_t addr) {
    asm volatile("ldmatrix.sync.aligned.m8n8.x2.trans.shared.b16 {%0,%1}, [%2];"
        : "=r"(r[0]), "=r"(r[1]) : "r"(addr));
}
__device__ __forceinline__ void mma_f16(float* d, const uint32_t* a, const uint32_t* b) {
    asm volatile(
        "mma.sync.aligned.m16n8k16.row.col.f32.f16.f16.f32 "
        "{%0,%1,%2,%3}, {%4,%5,%6,%7}, {%8,%9}, {%0,%1,%2,%3};\n"
        : "+f"(d[0]), "+f"(d[1]), "+f"(d[2]), "+f"(d[3])
        : "r"(a[0]), "r"(a[1]), "r"(a[2]), "r"(a[3]), "r"(b[0]), "r"(b[1]));
}

// ---------------------------------------------------------------------------
// f32 -> fp16 hi(/lo) convert. lo may be null (A-side-only tensors).
// ---------------------------------------------------------------------------
__global__ void cvt_split_kernel(const float* __restrict__ x,
                                 f16* __restrict__ hi, f16* __restrict__ lo,
                                 long long n4) {
    long long i = blockIdx.x * (long long)blockDim.x + threadIdx.x;
    if (i >= n4) return;
    float4 v = ((const float4*)x)[i];
    f16 h0, l0, h1, l1, h2, l2, h3, l3;
    split2h(v.x, h0, l0); split2h(v.y, h1, l1);
    split2h(v.z, h2, l2); split2h(v.w, h3, l3);
    ((f162*)hi)[i * 2]     = __halves2half2(h0, h1);
    ((f162*)hi)[i * 2 + 1] = __halves2half2(h2, h3);
    if (lo) {
        ((f162*)lo)[i * 2]     = __halves2half2(l0, l1);
        ((f162*)lo)[i * 2 + 1] = __halves2half2(l2, l3);
    }
}

// ---------------------------------------------------------------------------
// LayerNorm -> fp16 hi only (A-side)
// ---------------------------------------------------------------------------
__global__ void ln_kernel(const float* __restrict__ x, const float* __restrict__ g,
                          const float* __restrict__ b, f16* __restrict__ oh) {
    __shared__ float sh[32];
    long long row = blockIdx.x;
    float4 v = ((const float4*)(x + row * EE))[threadIdx.x];
    float s  = v.x + v.y + v.z + v.w;
    float sq = v.x * v.x + v.y * v.y + v.z * v.z + v.w * v.w;
    s  = blockSum(s,  sh);
    sq = blockSum(sq, sh);
    float mean = s * (1.f / EE);
    float var  = sq * (1.f / EE) - mean * mean;
    float inv  = rsqrtf(var + 1e-5f);
    float4 gv = ((const float4*)g)[threadIdx.x];
    float4 bv = ((const float4*)b)[threadIdx.x];
    float o0 = (v.x - mean) * inv * gv.x + bv.x;
    float o1 = (v.y - mean) * inv * gv.y + bv.y;
    float o2 = (v.z - mean) * inv * gv.z + bv.z;
    float o3 = (v.w - mean) * inv * gv.w + bv.w;
    f162* ph = (f162*)(oh + row * EE);
    ph[threadIdx.x * 2]     = __halves2half2(__float2half_rn(o0), __float2half_rn(o1));
    ph[threadIdx.x * 2 + 1] = __halves2half2(__float2half_rn(o2), __float2half_rn(o3));
}

// ---------------------------------------------------------------------------
// Softmax over S=2048 -> fp16 probs (hi only). Selects on mask value so
// skipped (never-written) score tiles are never consumed.
// ---------------------------------------------------------------------------
__global__ void softmax_kernel(const float* __restrict__ s, const float* __restrict__ mask,
                               f16* __restrict__ oh) {
    __shared__ float sh[32];
    long long row = blockIdx.x;
    int l = (int)(row & (LQ - 1));
    const float4* sr = (const float4*)(s + row * (long long)SK);
    float4 va = sr[threadIdx.x];
    float4 vb = sr[threadIdx.x + 256];
    if (mask) {
        const float4* mr = (const float4*)(mask + (long long)l * SK);
        float4 ma = mr[threadIdx.x], mb = mr[threadIdx.x + 256];
        va.x = (ma.x < -1e8f) ? -3.0e38f : va.x;
        va.y = (ma.y < -1e8f) ? -3.0e38f : va.y;
        va.z = (ma.z < -1e8f) ? -3.0e38f : va.z;
        va.w = (ma.w < -1e8f) ? -3.0e38f : va.w;
        vb.x = (mb.x < -1e8f) ? -3.0e38f : vb.x;
        vb.y = (mb.y < -1e8f) ? -3.0e38f : vb.y;
        vb.z = (mb.z < -1e8f) ? -3.0e38f : vb.z;
        vb.w = (mb.w < -1e8f) ? -3.0e38f : vb.w;
    }
    float mx = fmaxf(fmaxf(fmaxf(va.x, va.y), fmaxf(va.z, va.w)),
                     fmaxf(fmaxf(vb.x, vb.y), fmaxf(vb.z, vb.w)));
    mx = blockMax(mx, sh);
    va.x = __expf(va.x - mx); va.y = __expf(va.y - mx);
    va.z = __expf(va.z - mx); va.w = __expf(va.w - mx);
    vb.x = __expf(vb.x - mx); vb.y = __expf(vb.y - mx);
    vb.z = __expf(vb.z - mx); vb.w = __expf(vb.w - mx);
    float sum = va.x + va.y + va.z + va.w + vb.x + vb.y + vb.z + vb.w;
    sum = blockSum(sum, sh);
    float inv = 1.f / sum;
    f162* ph = (f162*)(oh + row * (long long)SK);
    ph[threadIdx.x * 2] = __halves2half2(__float2half_rn(va.x * inv), __float2half_rn(va.y * inv));
    ph[threadIdx.x * 2 + 1] = __halves2half2(__float2half_rn(va.z * inv), __float2half_rn(va.w * inv));
    ph[(threadIdx.x + 256) * 2] = __halves2half2(__float2half_rn(vb.x * inv), __float2half_rn(vb.y * inv));
    ph[(threadIdx.x + 256) * 2 + 1] = __halves2half2(__float2half_rn(vb.z * inv), __float2half_rn(vb.w * inv));
}

// ---------------------------------------------------------------------------
// Tensor-core GEMM, 2-term fp16 split: C = epi(Ah @ op(Bh + Bl)).
// 128x128 CTA tile, BK=32, 256 threads (2x4 warps), 64x32 warp tile, 2 CTA/SM.
// TRANSB=1: B is [N,K] row-major. TRANSB=0: B is [K,N].
// OUT: 0 = f32 (+res), 1 = split hi/lo fp16, 3 = hi-only fp16.
// CAUSAL: 0 none, 1 = K-loop truncated at bm+128 (P@V), 2 = skip tiles bn>bm.
// smem: 2 stages x (A 10240 + Bh 10240 + Bl 10240) = 61440 bytes.
// ---------------------------------------------------------------------------
#define BH_OFF 10240u
#define BL_OFF 20480u
#define STAGE  30720u
#define SMEMSZ (2u * STAGE)

template <int TRANSB, int ACT, int OUT, int CAUSAL>
__global__ void __launch_bounds__(256, 2)
gemm_tc(const f16* __restrict__ Ah,
        const f16* __restrict__ Bh, const f16* __restrict__ Bl,
        const float* __restrict__ bias, const float* __restrict__ res,
        float* C, f16* Ch, f16* Cl,
        int K, int lda, int ldb, int ldc,
        long long sA, long long sB, long long sC, float alpha) {
    const int bm = blockIdx.y * 128;
    const int bn = blockIdx.x * 128;
    if (CAUSAL == 2 && bn > bm) return;     // fully-masked score tile

    Ah += (long long)blockIdx.z * sA;
    Bh += (long long)blockIdx.z * sB;  Bl += (long long)blockIdx.z * sB;
    if (OUT == 0) { C  += (long long)blockIdx.z * sC; if (res) res += (long long)blockIdx.z * sC; }
    else          { Ch += (long long)blockIdx.z * sC; if (OUT == 1) Cl += (long long)blockIdx.z * sC; }

    extern __shared__ f16 smem[];
    const uint32_t sbase = (uint32_t)__cvta_generic_to_shared(smem);
    const int tid  = threadIdx.x;
    const int lane = tid & 31;
    const int warp = tid >> 5;
    const int wm = warp >> 2;   // 0..1
    const int wn = warp & 3;    // 0..3

    float acc[4][4][4];
#pragma unroll
    for (int i = 0; i < 4; i++)
#pragma unroll
        for (int j = 0; j < 4; j++)
#pragma unroll
            for (int q = 0; q < 4; q++) acc[i][j][q] = 0.f;

    auto load_stage = [&](int st, int k0) {
        uint32_t sb = sbase + (uint32_t)st * STAGE;
#pragma unroll
        for (int i = 0; i < 2; i++) {               // A: 128 rows x 4 16B chunks
            int c = tid + i * 256;
            int row = c >> 2, kc = c & 3;
            size_t off = (size_t)(bm + row) * lda + k0 + kc * 8;
            cpa16(sb + row * 80 + kc * 16, Ah + off);
        }
        if (TRANSB) {
#pragma unroll
            for (int i = 0; i < 2; i++) {           // B: 128 rows x 4 chunks, hi+lo
                int c = tid + i * 256;
                int row = c >> 2, kc = c & 3;
                size_t off = (size_t)(bn + row) * ldb + k0 + kc * 8;
                uint32_t d = sb + BH_OFF + row * 80 + kc * 16;
                cpa16(d, Bh + off);
                cpa16(d + (BL_OFF - BH_OFF), Bl + off);
            }
        } else {
#pragma unroll
            for (int i = 0; i < 2; i++) {           // B: 32 k-rows x 16 chunks, hi+lo
                int c = tid + i * 256;
                int row = c >> 4, nc = c & 15;
                size_t off = (size_t)(k0 + row) * ldb + bn + nc * 8;
                uint32_t d = sb + BH_OFF + row * 272 + nc * 16;
                cpa16(d, Bh + off);
                cpa16(d + (BL_OFF - BH_OFF), Bl + off);
            }
        }
        CP_COMMIT();
    };

    auto compute_stage = [&](int st) {
        uint32_t sA_ = sbase + (uint32_t)st * STAGE;
        uint32_t sB_ = sA_ + BH_OFF;
#pragma unroll
        for (int ks = 0; ks < 2; ks++) {
            const int k16 = ks * 16;
            uint32_t ah[4][4], bh[4][2], bl[4][2];
            const int arow = lane & 15;
            const int acol = k16 + (lane >> 4) * 8;
#pragma unroll
            for (int mt = 0; mt < 4; mt++) {
                uint32_t addr = sA_ + (uint32_t)((wm * 64 + mt * 16 + arow) * 80 + acol * 2);
                ldsm4(ah[mt], addr);
            }
            if (TRANSB) {
                const int brow = lane & 7;
                const int bk   = k16 + ((lane >> 3) & 1) * 8;
#pragma unroll
                for (int nt = 0; nt < 4; nt++) {
                    uint32_t addr = sB_ + (uint32_t)((wn * 32 + nt * 8 + brow) * 80 + bk * 2);
                    ldsm2(bh[nt], addr);
                    ldsm2(bl[nt], addr + (BL_OFF - BH_OFF));
                }
            } else {
                const int brow = k16 + (lane & 15);
#pragma unroll
                for (int nt = 0; nt < 4; nt++) {
                    uint32_t addr = sB_ + (uint32_t)(brow * 272 + (wn * 32 + nt * 8) * 2);
                    ldsm2t(bh[nt], addr);
                    ldsm2t(bl[nt], addr + (BL_OFF - BH_OFF));
                }
            }
#pragma unroll
            for (int mt = 0; mt < 4; mt++)
#pragma unroll
                for (int nt = 0; nt < 4; nt++) {
                    mma_f16(acc[mt][nt], ah[mt], bh[nt]);
                    mma_f16(acc[mt][nt], ah[mt], bl[nt]);
                }
        }
    };

    const int Kend = (CAUSAL == 1) ? min(K, bm + 128) : K;
    const int KT = Kend >> 5;
    load_stage(0, 0);
    for (int kt = 0; kt < KT; kt++) {
        if (kt + 1 < KT) { load_stage((kt + 1) & 1, (kt + 1) * 32); CP_WAIT1(); }
        else             { CP_WAIT0(); }
        __syncthreads();
        compute_stage(kt & 1);
        __syncthreads();
    }

    // Epilogue
#pragma unroll
    for (int mt = 0; mt < 4; mt++) {
        const int r0 = bm + wm * 64 + mt * 16 + (lane >> 2);
#pragma unroll
        for (int nt = 0; nt < 4; nt++) {
            const int c = bn + wn * 32 + nt * 8 + (lane & 3) * 2;
            float bc0 = 0.f, bc1 = 0.f;
            if (bias) { bc0 = bias[c]; bc1 = bias[c + 1]; }
#pragma unroll
            for (int h = 0; h < 2; h++) {
                float v0 = acc[mt][nt][h * 2 + 0] + bc0;
                float v1 = acc[mt][nt][h * 2 + 1] + bc1;
                v0 *= alpha; v1 *= alpha;
                if (ACT == 1) {
                    v0 = v0 / (1.f + __expf(-1.702f * v0));
                    v1 = v1 / (1.f + __expf(-1.702f * v1));
                }
                const size_t row = (size_t)(r0 + h * 8);
                if (OUT == 0) {
                    if (res) {
                        const float2 rv = *(const float2*)(res + row * ldc + c);
                        v0 += rv.x; v1 += rv.y;
                    }
                    *(float2*)(C + row * ldc + c) = make_float2(v0, v1);
                } else if (OUT == 1) {
                    f16 h0, l0, h1, l1;
                    split2h(v0, h0, l0); split2h(v1, h1, l1);
                    *(f162*)(Ch + row * ldc + c) = __halves2half2(h0, h1);
                    *(f162*)(Cl + row * ldc + c) = __halves2half2(l0, l1);
                } else {  // OUT == 3: hi only
                    *(f162*)(Ch + row * ldc + c) =
                        __halves2half2(__float2half_rn(v0), __float2half_rn(v1));
                }
            }
        }
    }
}

// ---------------------------------------------------------------------------
// Host launcher
// ---------------------------------------------------------------------------
extern "C" void kernel_launch(void* const* d_in, const int* in_sizes, int n_in,
                              void* d_out, int out_size) {
    const float* tgt    = (const float*)d_in[0];
    const float* memory = (const float*)d_in[1];
    const float* mask   = (const float*)d_in[2];
    const float* sa_qw  = (const float*)d_in[3];
    const float* sa_kw  = (const float*)d_in[4];
    const float* sa_vw  = (const float*)d_in[5];
    const float* sa_b   = (const float*)d_in[6];
    const float* sa_ow  = (const float*)d_in[7];
    const float* sa_ob  = (const float*)d_in[8];
    const float* ca_qw  = (const float*)d_in[9];
    const float* ca_kw  = (const float*)d_in[10];
    const float* ca_vw  = (const float*)d_in[11];
    const float* ca_b   = (const float*)d_in[12];
    const float* ca_ow  = (const float*)d_in[13];
    const float* ca_ob  = (const float*)d_in[14];
    const float* ln1_g  = (const float*)d_in[15];
    const float* ln1_b  = (const float*)d_in[16];
    const float* ln2_g  = (const float*)d_in[17];
    const float* ln2_b  = (const float*)d_in[18];
    const float* ln3_g  = (const float*)d_in[19];
    const float* ln3_b  = (const float*)d_in[20];
    const float* w1     = (const float*)d_in[21];
    const float* b1     = (const float*)d_in[22];
    const float* w2     = (const float*)d_in[23];
    const float* b2     = (const float*)d_in[24];
    float* x = (float*)d_out;

    f16 *hh, *qh, *kh, *kl, *vh, *vl, *ph, *abh, *ffh, *wh, *wl, *mh;
    float* sb;
    cudaGetSymbolAddress((void**)&hh,  s_hh);
    cudaGetSymbolAddress((void**)&qh,  s_qh);
    cudaGetSymbolAddress((void**)&kh,  s_kh);  cudaGetSymbolAddress((void**)&kl,  s_kl);
    cudaGetSymbolAddress((void**)&vh,  s_vh);  cudaGetSymbolAddress((void**)&vl,  s_vl);
    cudaGetSymbolAddress((void**)&ph,  s_ph);
    cudaGetSymbolAddress((void**)&abh, s_abh);
    cudaGetSymbolAddress((void**)&ffh, s_ffh);
    cudaGetSymbolAddress((void**)&wh,  s_wh);  cudaGetSymbolAddress((void**)&wl,  s_wl);
    cudaGetSymbolAddress((void**)&mh,  s_mh);
    cudaGetSymbolAddress((void**)&sb,  g_s);

    cudaFuncSetAttribute(gemm_tc<1, 0, 3, 0>, cudaFuncAttributeMaxDynamicSharedMemorySize, SMEMSZ);
    cudaFuncSetAttribute(gemm_tc<1, 0, 1, 0>, cudaFuncAttributeMaxDynamicSharedMemorySize, SMEMSZ);
    cudaFuncSetAttribute(gemm_tc<1, 0, 0, 0>, cudaFuncAttributeMaxDynamicSharedMemorySize, SMEMSZ);
    cudaFuncSetAttribute(gemm_tc<1, 0, 0, 2>, cudaFuncAttributeMaxDynamicSharedMemorySize, SMEMSZ);
    cudaFuncSetAttribute(gemm_tc<0, 0, 3, 0>, cudaFuncAttributeMaxDynamicSharedMemorySize, SMEMSZ);
    cudaFuncSetAttribute(gemm_tc<0, 0, 3, 1>, cudaFuncAttributeMaxDynamicSharedMemorySize, SMEMSZ);
    cudaFuncSetAttribute(gemm_tc<1, 1, 3, 0>, cudaFuncAttributeMaxDynamicSharedMemorySize, SMEMSZ);

    const float scale = 1.0f / 32.0f;
    const long long SBATCH = (long long)LQ * SK;

    cudaMemcpyAsync(x, tgt, (size_t)MTOK * EE * sizeof(float),
                    cudaMemcpyDeviceToDevice, 0);

    dim3 gProj(EE / 128, MTOK / 128);       // (8, 64)
    dim3 gScore(SK / 128, LQ / 128, NB);    // (16, 16, 4)
    dim3 gPV(EE / 128, LQ / 128, NB);       // (8, 16, 4)
    dim3 gFF1(FFD / 128, MTOK / 128);       // (32, 64)

    const long long nW1 = (long long)EE * EE / 4;
    const long long nFF = (long long)FFD * EE / 4;
    const long long nM  = (long long)MTOK * EE / 4;

#define CVT(src, dh, dl, n4) cvt_split_kernel<<<(unsigned)((n4) / 256), 256>>>(src, dh, dl, n4)

    // ---------------- self-attention ----------------
    ln_kernel<<<MTOK, 256>>>(x, ln1_g, ln1_b, hh);
    CVT(sa_qw, wh, wl, nW1);
    gemm_tc<1, 0, 3, 0><<<gProj, 256, SMEMSZ>>>(hh, wh, wl, sa_b, nullptr,
        nullptr, qh, nullptr, EE, EE, EE, EE, 0, 0, 0, scale);
    CVT(sa_kw, wh, wl, nW1);
    gemm_tc<1, 0, 1, 0><<<gProj, 256, SMEMSZ>>>(hh, wh, wl, sa_b + EE, nullptr,
        nullptr, kh, kl, EE, EE, EE, EE, 0, 0, 0, 1.f);
    CVT(sa_vw, wh, wl, nW1);
    gemm_tc<1, 0, 1, 0><<<gProj, 256, SMEMSZ>>>(hh, wh, wl, sa_b + 2 * EE, nullptr,
        nullptr, vh, vl, EE, EE, EE, EE, 0, 0, 0, 1.f);
    // causal scores (upper tiles skipped)
    gemm_tc<1, 0, 0, 2><<<gScore, 256, SMEMSZ>>>(qh, kh, kl, nullptr, nullptr,
        sb, nullptr, nullptr, EE, NB * EE, NB * EE, SK, EE, EE, SBATCH, 1.f);
    softmax_kernel<<<NB * LQ, 256>>>(sb, mask, ph);
    // causal P@V (K-loop truncated)
    gemm_tc<0, 0, 3, 1><<<gPV, 256, SMEMSZ>>>(ph, vh, vl, nullptr, nullptr,
        nullptr, abh, nullptr, SK, SK, NB * EE, NB * EE, SBATCH, EE, EE, 1.f);
    CVT(sa_ow, wh, wl, nW1);
    gemm_tc<1, 0, 0, 0><<<gProj, 256, SMEMSZ>>>(abh, wh, wl, sa_ob, x,
        x, nullptr, nullptr, EE, EE, EE, EE, 0, 0, 0, 1.f);

    // ---------------- cross-attention ----------------
    ln_kernel<<<MTOK, 256>>>(x, ln2_g, ln2_b, hh);
    CVT(memory, mh, nullptr, nM);
    CVT(ca_qw, wh, wl, nW1);
    gemm_tc<1, 0, 3, 0><<<gProj, 256, SMEMSZ>>>(hh, wh, wl, ca_b, nullptr,
        nullptr, qh, nullptr, EE, EE, EE, EE, 0, 0, 0, scale);
    CVT(ca_kw, wh, wl, nW1);
    gemm_tc<1, 0, 1, 0><<<gProj, 256, SMEMSZ>>>(mh, wh, wl, ca_b + EE, nullptr,
        nullptr, kh, kl, EE, EE, EE, EE, 0, 0, 0, 1.f);
    CVT(ca_vw, wh, wl, nW1);
    gemm_tc<1, 0, 1, 0><<<gProj, 256, SMEMSZ>>>(mh, wh, wl, ca_b + 2 * EE, nullptr,
        nullptr, vh, vl, EE, EE, EE, EE, 0, 0, 0, 1.f);
    gemm_tc<1, 0, 0, 0><<<gScore, 256, SMEMSZ>>>(qh, kh, kl, nullptr, nullptr,
        sb, nullptr, nullptr, EE, NB * EE, NB * EE, SK, EE, EE, SBATCH, 1.f);
    softmax_kernel<<<NB * LQ, 256>>>(sb, nullptr, ph);
    gemm_tc<0, 0, 3, 0><<<gPV, 256, SMEMSZ>>>(ph, vh, vl, nullptr, nullptr,
        nullptr, abh, nullptr, SK, SK, NB * EE, NB * EE, SBATCH, EE, EE, 1.f);
    CVT(ca_ow, wh, wl, nW1);
    gemm_tc<1, 0, 0, 0><<<gProj, 256, SMEMSZ>>>(abh, wh, wl, ca_ob, x,
        x, nullptr, nullptr, EE, EE, EE, EE, 0, 0, 0, 1.f);

    // ---------------- MLP ----------------
    ln_kernel<<<MTOK, 256>>>(x, ln3_g, ln3_b, hh);
    CVT(w1, wh, wl, nFF);
    gemm_tc<1, 1, 3, 0><<<gFF1, 256, SMEMSZ>>>(hh, wh, wl, b1, nullptr,
        nullptr, ffh, nullptr, EE, EE, EE, FFD, 0, 0, 0, 1.f);
    CVT(w2, wh, wl, nFF);
    gemm_tc<1, 0, 0, 0><<<gProj, 256, SMEMSZ>>>(ffh, wh, wl, b2, x,
        x, nullptr, nullptr, FFD, FFD, FFD, EE, 0, 0, 0, 1.f);
#undef CVT
}

// round 6
// speedup vs baseline: 11.1024x; 1.6973x over previous
#include <cuda_runtime.h>
#include <cuda_fp16.h>
#include <math.h>
#include <stdint.h>

#define LQ   2048
#define SK   2048
#define NB   4
#define EE   1024
#define FFD  4096
#define MTOK (LQ * NB)

typedef __half  f16;
typedef __half2 f162;

// ---------------------------------------------------------------------------
// Scratch (device globals) — all fp16 single precision copies
// ---------------------------------------------------------------------------
__device__ f16 s_hh [(size_t)MTOK * EE];       // LN out
__device__ f16 s_qh [(size_t)MTOK * EE];
__device__ f16 s_kh [(size_t)MTOK * EE];
__device__ f16 s_vh [(size_t)MTOK * EE];
__device__ f16 s_ph [(size_t)NB * LQ * SK];    // probs
__device__ f16 s_abh[(size_t)MTOK * EE];       // attn out
__device__ f16 s_ffh[(size_t)MTOK * FFD];      // MLP hidden
__device__ f16 s_wh [(size_t)FFD * EE];        // current weight
__device__ f16 s_mh [(size_t)MTOK * EE];       // memory
__device__ float g_s [(size_t)NB * LQ * SK];   // f32 scores

// ---------------------------------------------------------------------------
// Helpers
// ---------------------------------------------------------------------------
__device__ __forceinline__ float warpSum(float v) {
#pragma unroll
    for (int o = 16; o > 0; o >>= 1) v += __shfl_xor_sync(0xffffffffu, v, o);
    return v;
}
__device__ __forceinline__ float warpMax(float v) {
#pragma unroll
    for (int o = 16; o > 0; o >>= 1) v = fmaxf(v, __shfl_xor_sync(0xffffffffu, v, o));
    return v;
}
__device__ __forceinline__ float blockSum(float v, float* sh) {
    int lane = threadIdx.x & 31, wid = threadIdx.x >> 5;
    v = warpSum(v);
    if (lane == 0) sh[wid] = v;
    __syncthreads();
    float r = (lane < 8) ? sh[lane] : 0.f;
    r = warpSum(r);
    __syncthreads();
    return r;
}
__device__ __forceinline__ float blockMax(float v, float* sh) {
    int lane = threadIdx.x & 31, wid = threadIdx.x >> 5;
    v = warpMax(v);
    if (lane == 0) sh[wid] = v;
    __syncthreads();
    float r = (lane < 8) ? sh[lane] : -3.4e38f;
    r = warpMax(r);
    __syncthreads();
    return r;
}

// ---------------------------------------------------------------------------
// PTX wrappers (sm_80-class features only — compute_103-safe)
// ---------------------------------------------------------------------------
__device__ __forceinline__ void cpa16(uint32_t dst, const void* src) {
    asm volatile("cp.async.cg.shared.global [%0], [%1], 16;" :: "r"(dst), "l"(src));
}
#define CP_COMMIT() asm volatile("cp.async.commit_group;" ::: "memory")
#define CP_WAIT0()  asm volatile("cp.async.wait_group 0;" ::: "memory")
#define CP_WAIT1()  asm volatile("cp.async.wait_group 1;" ::: "memory")

__device__ __forceinline__ void ldsm4(uint32_t* r, uint32_t addr) {
    asm volatile("ldmatrix.sync.aligned.m8n8.x4.shared.b16 {%0,%1,%2,%3}, [%4];"
        : "=r"(r[0]), "=r"(r[1]), "=r"(r[2]), "=r"(r[3]) : "r"(addr));
}
__device__ __forceinline__ void ldsm2(uint32_t* r, uint32_t addr) {
    asm volatile("ldmatrix.sync.aligned.m8n8.x2.shared.b16 {%0,%1}, [%2];"
        : "=r"(r[0]), "=r"(r[1]) : "r"(addr));
}
__device__ __forceinline__ void ldsm2t(uint32_t* r, uint32_t addr) {
    asm volatile("ldmatrix.sync.aligned.m8n8.x2.trans.shared.b16 {%0,%1}, [%2];"
        : "=r"(r[0]), "=r"(r[1]) : "r"(addr));
}
__device__ __forceinline__ void mma_f16(float* d, const uint32_t* a, const uint32_t* b) {
    asm volatile(
        "mma.sync.aligned.m16n8k16.row.col.f32.f16.f16.f32 "
        "{%0,%1,%2,%3}, {%4,%5,%6,%7}, {%8,%9}, {%0,%1,%2,%3};\n"
        : "+f"(d[0]), "+f"(d[1]), "+f"(d[2]), "+f"(d[3])
        : "r"(a[0]), "r"(a[1]), "r"(a[2]), "r"(a[3]), "r"(b[0]), "r"(b[1]));
}

// ---------------------------------------------------------------------------
// f32 -> fp16 convert
// ---------------------------------------------------------------------------
__global__ void cvt_kernel(const float* __restrict__ x, f16* __restrict__ o,
                           long long n4) {
    long long i = blockIdx.x * (long long)blockDim.x + threadIdx.x;
    if (i >= n4) return;
    float4 v = ((const float4*)x)[i];
    ((f162*)o)[i * 2]     = __halves2half2(__float2half_rn(v.x), __float2half_rn(v.y));
    ((f162*)o)[i * 2 + 1] = __halves2half2(__float2half_rn(v.z), __float2half_rn(v.w));
}

// ---------------------------------------------------------------------------
// LayerNorm -> fp16
// ---------------------------------------------------------------------------
__global__ void ln_kernel(const float* __restrict__ x, const float* __restrict__ g,
                          const float* __restrict__ b, f16* __restrict__ oh) {
    __shared__ float sh[32];
    long long row = blockIdx.x;
    float4 v = ((const float4*)(x + row * EE))[threadIdx.x];
    float s  = v.x + v.y + v.z + v.w;
    float sq = v.x * v.x + v.y * v.y + v.z * v.z + v.w * v.w;
    s  = blockSum(s,  sh);
    sq = blockSum(sq, sh);
    float mean = s * (1.f / EE);
    float var  = sq * (1.f / EE) - mean * mean;
    float inv  = rsqrtf(var + 1e-5f);
    float4 gv = ((const float4*)g)[threadIdx.x];
    float4 bv = ((const float4*)b)[threadIdx.x];
    float o0 = (v.x - mean) * inv * gv.x + bv.x;
    float o1 = (v.y - mean) * inv * gv.y + bv.y;
    float o2 = (v.z - mean) * inv * gv.z + bv.z;
    float o3 = (v.w - mean) * inv * gv.w + bv.w;
    f162* ph = (f162*)(oh + row * EE);
    ph[threadIdx.x * 2]     = __halves2half2(__float2half_rn(o0), __float2half_rn(o1));
    ph[threadIdx.x * 2 + 1] = __halves2half2(__float2half_rn(o2), __float2half_rn(o3));
}

// ---------------------------------------------------------------------------
// Softmax over S=2048 -> fp16 probs. Mask-select so skipped score tiles are
// never consumed.
// ---------------------------------------------------------------------------
__global__ void softmax_kernel(const float* __restrict__ s, const float* __restrict__ mask,
                               f16* __restrict__ oh) {
    __shared__ float sh[32];
    long long row = blockIdx.x;
    int l = (int)(row & (LQ - 1));
    const float4* sr = (const float4*)(s + row * (long long)SK);
    float4 va = sr[threadIdx.x];
    float4 vb = sr[threadIdx.x + 256];
    if (mask) {
        const float4* mr = (const float4*)(mask + (long long)l * SK);
        float4 ma = mr[threadIdx.x], mb = mr[threadIdx.x + 256];
        va.x = (ma.x < -1e8f) ? -3.0e38f : va.x;
        va.y = (ma.y < -1e8f) ? -3.0e38f : va.y;
        va.z = (ma.z < -1e8f) ? -3.0e38f : va.z;
        va.w = (ma.w < -1e8f) ? -3.0e38f : va.w;
        vb.x = (mb.x < -1e8f) ? -3.0e38f : vb.x;
        vb.y = (mb.y < -1e8f) ? -3.0e38f : vb.y;
        vb.z = (mb.z < -1e8f) ? -3.0e38f : vb.z;
        vb.w = (mb.w < -1e8f) ? -3.0e38f : vb.w;
    }
    float mx = fmaxf(fmaxf(fmaxf(va.x, va.y), fmaxf(va.z, va.w)),
                     fmaxf(fmaxf(vb.x, vb.y), fmaxf(vb.z, vb.w)));
    mx = blockMax(mx, sh);
    va.x = __expf(va.x - mx); va.y = __expf(va.y - mx);
    va.z = __expf(va.z - mx); va.w = __expf(va.w - mx);
    vb.x = __expf(vb.x - mx); vb.y = __expf(vb.y - mx);
    vb.z = __expf(vb.z - mx); vb.w = __expf(vb.w - mx);
    float sum = va.x + va.y + va.z + va.w + vb.x + vb.y + vb.z + vb.w;
    sum = blockSum(sum, sh);
    float inv = 1.f / sum;
    f162* ph = (f162*)(oh + row * (long long)SK);
    ph[threadIdx.x * 2] = __halves2half2(__float2half_rn(va.x * inv), __float2half_rn(va.y * inv));
    ph[threadIdx.x * 2 + 1] = __halves2half2(__float2half_rn(va.z * inv), __float2half_rn(va.w * inv));
    ph[(threadIdx.x + 256) * 2] = __halves2half2(__float2half_rn(vb.x * inv), __float2half_rn(vb.y * inv));
    ph[(threadIdx.x + 256) * 2 + 1] = __halves2half2(__float2half_rn(vb.z * inv), __float2half_rn(vb.w * inv));
}

// ---------------------------------------------------------------------------
// Tensor-core GEMM, single-term fp16: C = epi(A @ op(B)).
// 128x128 CTA tile, BK=32, 256 threads (2x4 warps), 64x32 warp tile.
// 3-stage cp.async pipeline, one __syncthreads per K-step, 2 CTA/SM.
// TRANSB=1: B [N,K] row-major. TRANSB=0: B [K,N].
// OUT: 0 = f32 (+res), 3 = fp16.
// CAUSAL: 0 none, 1 = K truncated at bm+128 (P@V), 2 = skip tiles bn>bm.
// smem: 3 stages x (A 10240 + B 10240) = 61440 bytes.
// ---------------------------------------------------------------------------
#define B_OFF  10240u
#define STAGE  20480u
#define SMEMSZ (3u * STAGE)

template <int TRANSB, int ACT, int OUT, int CAUSAL>
__global__ void __launch_bounds__(256, 2)
gemm_tc(const f16* __restrict__ Ah, const f16* __restrict__ Bh,
        const float* __restrict__ bias, const float* __restrict__ res,
        float* C, f16* Ch,
        int K, int lda, int ldb, int ldc,
        long long sA, long long sB, long long sC, float alpha) {
    const int bm = blockIdx.y * 128;
    const int bn = blockIdx.x * 128;
    if (CAUSAL == 2 && bn > bm) return;     // fully-masked score tile

    Ah += (long long)blockIdx.z * sA;
    Bh += (long long)blockIdx.z * sB;
    if (OUT == 0) { C  += (long long)blockIdx.z * sC; if (res) res += (long long)blockIdx.z * sC; }
    else          { Ch += (long long)blockIdx.z * sC; }

    extern __shared__ f16 smem[];
    const uint32_t sbase = (uint32_t)__cvta_generic_to_shared(smem);
    const int tid  = threadIdx.x;
    const int lane = tid & 31;
    const int warp = tid >> 5;
    const int wm = warp >> 2;   // 0..1
    const int wn = warp & 3;    // 0..3

    float acc[4][4][4];
#pragma unroll
    for (int i = 0; i < 4; i++)
#pragma unroll
        for (int j = 0; j < 4; j++)
#pragma unroll
            for (int q = 0; q < 4; q++) acc[i][j][q] = 0.f;

    auto load_stage = [&](int st, int k0) {
        uint32_t sb = sbase + (uint32_t)st * STAGE;
#pragma unroll
        for (int i = 0; i < 2; i++) {               // A: 128 rows x 4 16B chunks
            int c = tid + i * 256;
            int row = c >> 2, kc = c & 3;
            size_t off = (size_t)(bm + row) * lda + k0 + kc * 8;
            cpa16(sb + row * 80 + kc * 16, Ah + off);
        }
        if (TRANSB) {
#pragma unroll
            for (int i = 0; i < 2; i++) {           // B: 128 rows x 4 chunks
                int c = tid + i * 256;
                int row = c >> 2, kc = c & 3;
                size_t off = (size_t)(bn + row) * ldb + k0 + kc * 8;
                cpa16(sb + B_OFF + row * 80 + kc * 16, Bh + off);
            }
        } else {
#pragma unroll
            for (int i = 0; i < 2; i++) {           // B: 32 k-rows x 16 chunks
                int c = tid + i * 256;
                int row = c >> 4, nc = c & 15;
                size_t off = (size_t)(k0 + row) * ldb + bn + nc * 8;
                cpa16(sb + B_OFF + row * 272 + nc * 16, Bh + off);
            }
        }
        CP_COMMIT();
    };

    auto compute_stage = [&](int st) {
        uint32_t sA_ = sbase + (uint32_t)st * STAGE;
        uint32_t sB_ = sA_ + B_OFF;
#pragma unroll
        for (int ks = 0; ks < 2; ks++) {
            const int k16 = ks * 16;
            uint32_t ah[4][4], bh[4][2];
            const int arow = lane & 15;
            const int acol = k16 + (lane >> 4) * 8;
#pragma unroll
            for (int mt = 0; mt < 4; mt++) {
                uint32_t addr = sA_ + (uint32_t)((wm * 64 + mt * 16 + arow) * 80 + acol * 2);
                ldsm4(ah[mt], addr);
            }
            if (TRANSB) {
                const int brow = lane & 7;
                const int bk   = k16 + ((lane >> 3) & 1) * 8;
#pragma unroll
                for (int nt = 0; nt < 4; nt++) {
                    uint32_t addr = sB_ + (uint32_t)((wn * 32 + nt * 8 + brow) * 80 + bk * 2);
                    ldsm2(bh[nt], addr);
                }
            } else {
                const int brow = k16 + (lane & 15);
#pragma unroll
                for (int nt = 0; nt < 4; nt++) {
                    uint32_t addr = sB_ + (uint32_t)(brow * 272 + (wn * 32 + nt * 8) * 2);
                    ldsm2t(bh[nt], addr);
                }
            }
#pragma unroll
            for (int mt = 0; mt < 4; mt++)
#pragma unroll
                for (int nt = 0; nt < 4; nt++)
                    mma_f16(acc[mt][nt], ah[mt], bh[nt]);
        }
    };

    const int Kend = (CAUSAL == 1) ? min(K, bm + 128) : K;
    const int KT = Kend >> 5;
    load_stage(0, 0);
    if (KT > 1) load_stage(1, 32);
    for (int kt = 0; kt < KT; kt++) {
        if (kt + 1 < KT) CP_WAIT1(); else CP_WAIT0();
        __syncthreads();
        if (kt + 2 < KT) load_stage((kt + 2) % 3, (kt + 2) * 32);
        compute_stage(kt % 3);
    }

    // Epilogue
#pragma unroll
    for (int mt = 0; mt < 4; mt++) {
        const int r0 = bm + wm * 64 + mt * 16 + (lane >> 2);
#pragma unroll
        for (int nt = 0; nt < 4; nt++) {
            const int c = bn + wn * 32 + nt * 8 + (lane & 3) * 2;
            float bc0 = 0.f, bc1 = 0.f;
            if (bias) { bc0 = bias[c]; bc1 = bias[c + 1]; }
#pragma unroll
            for (int h = 0; h < 2; h++) {
                float v0 = acc[mt][nt][h * 2 + 0] + bc0;
                float v1 = acc[mt][nt][h * 2 + 1] + bc1;
                v0 *= alpha; v1 *= alpha;
                if (ACT == 1) {
                    v0 = v0 / (1.f + __expf(-1.702f * v0));
                    v1 = v1 / (1.f + __expf(-1.702f * v1));
                }
                const size_t row = (size_t)(r0 + h * 8);
                if (OUT == 0) {
                    if (res) {
                        const float2 rv = *(const float2*)(res + row * ldc + c);
                        v0 += rv.x; v1 += rv.y;
                    }
                    *(float2*)(C + row * ldc + c) = make_float2(v0, v1);
                } else {
                    *(f162*)(Ch + row * ldc + c) =
                        __halves2half2(__float2half_rn(v0), __float2half_rn(v1));
                }
            }
        }
    }
}

// ---------------------------------------------------------------------------
// Host launcher
// ---------------------------------------------------------------------------
extern "C" void kernel_launch(void* const* d_in, const int* in_sizes, int n_in,
                              void* d_out, int out_size) {
    const float* tgt    = (const float*)d_in[0];
    const float* memory = (const float*)d_in[1];
    const float* mask   = (const float*)d_in[2];
    const float* sa_qw  = (const float*)d_in[3];
    const float* sa_kw  = (const float*)d_in[4];
    const float* sa_vw  = (const float*)d_in[5];
    const float* sa_b   = (const float*)d_in[6];
    const float* sa_ow  = (const float*)d_in[7];
    const float* sa_ob  = (const float*)d_in[8];
    const float* ca_qw  = (const float*)d_in[9];
    const float* ca_kw  = (const float*)d_in[10];
    const float* ca_vw  = (const float*)d_in[11];
    const float* ca_b   = (const float*)d_in[12];
    const float* ca_ow  = (const float*)d_in[13];
    const float* ca_ob  = (const float*)d_in[14];
    const float* ln1_g  = (const float*)d_in[15];
    const float* ln1_b  = (const float*)d_in[16];
    const float* ln2_g  = (const float*)d_in[17];
    const float* ln2_b  = (const float*)d_in[18];
    const float* ln3_g  = (const float*)d_in[19];
    const float* ln3_b  = (const float*)d_in[20];
    const float* w1     = (const float*)d_in[21];
    const float* b1     = (const float*)d_in[22];
    const float* w2     = (const float*)d_in[23];
    const float* b2     = (const float*)d_in[24];
    float* x = (float*)d_out;

    f16 *hh, *qh, *kh, *vh, *ph, *abh, *ffh, *wh, *mh;
    float* sb;
    cudaGetSymbolAddress((void**)&hh,  s_hh);
    cudaGetSymbolAddress((void**)&qh,  s_qh);
    cudaGetSymbolAddress((void**)&kh,  s_kh);
    cudaGetSymbolAddress((void**)&vh,  s_vh);
    cudaGetSymbolAddress((void**)&ph,  s_ph);
    cudaGetSymbolAddress((void**)&abh, s_abh);
    cudaGetSymbolAddress((void**)&ffh, s_ffh);
    cudaGetSymbolAddress((void**)&wh,  s_wh);
    cudaGetSymbolAddress((void**)&mh,  s_mh);
    cudaGetSymbolAddress((void**)&sb,  g_s);

    cudaFuncSetAttribute(gemm_tc<1, 0, 3, 0>, cudaFuncAttributeMaxDynamicSharedMemorySize, SMEMSZ);
    cudaFuncSetAttribute(gemm_tc<1, 0, 0, 0>, cudaFuncAttributeMaxDynamicSharedMemorySize, SMEMSZ);
    cudaFuncSetAttribute(gemm_tc<1, 0, 0, 2>, cudaFuncAttributeMaxDynamicSharedMemorySize, SMEMSZ);
    cudaFuncSetAttribute(gemm_tc<0, 0, 3, 0>, cudaFuncAttributeMaxDynamicSharedMemorySize, SMEMSZ);
    cudaFuncSetAttribute(gemm_tc<0, 0, 3, 1>, cudaFuncAttributeMaxDynamicSharedMemorySize, SMEMSZ);
    cudaFuncSetAttribute(gemm_tc<1, 1, 3, 0>, cudaFuncAttributeMaxDynamicSharedMemorySize, SMEMSZ);

    const float scale = 1.0f / 32.0f;
    const long long SBATCH = (long long)LQ * SK;

    cudaMemcpyAsync(x, tgt, (size_t)MTOK * EE * sizeof(float),
                    cudaMemcpyDeviceToDevice, 0);

    dim3 gProj(EE / 128, MTOK / 128);       // (8, 64)
    dim3 gScore(SK / 128, LQ / 128, NB);    // (16, 16, 4)
    dim3 gPV(EE / 128, LQ / 128, NB);       // (8, 16, 4)
    dim3 gFF1(FFD / 128, MTOK / 128);       // (32, 64)

    const long long nW1 = (long long)EE * EE / 4;
    const long long nFF = (long long)FFD * EE / 4;
    const long long nM  = (long long)MTOK * EE / 4;

#define CVT(src, dst, n4) cvt_kernel<<<(unsigned)((n4) / 256), 256>>>(src, dst, n4)

    // ---------------- self-attention ----------------
    ln_kernel<<<MTOK, 256>>>(x, ln1_g, ln1_b, hh);
    CVT(sa_qw, wh, nW1);
    gemm_tc<1, 0, 3, 0><<<gProj, 256, SMEMSZ>>>(hh, wh, sa_b, nullptr,
        nullptr, qh, EE, EE, EE, EE, 0, 0, 0, scale);
    CVT(sa_kw, wh, nW1);
    gemm_tc<1, 0, 3, 0><<<gProj, 256, SMEMSZ>>>(hh, wh, sa_b + EE, nullptr,
        nullptr, kh, EE, EE, EE, EE, 0, 0, 0, 1.f);
    CVT(sa_vw, wh, nW1);
    gemm_tc<1, 0, 3, 0><<<gProj, 256, SMEMSZ>>>(hh, wh, sa_b + 2 * EE, nullptr,
        nullptr, vh, EE, EE, EE, EE, 0, 0, 0, 1.f);
    // causal scores (upper tiles skipped)
    gemm_tc<1, 0, 0, 2><<<gScore, 256, SMEMSZ>>>(qh, kh, nullptr, nullptr,
        sb, nullptr, EE, NB * EE, NB * EE, SK, EE, EE, SBATCH, 1.f);
    softmax_kernel<<<NB * LQ, 256>>>(sb, mask, ph);
    // causal P@V (K truncated)
    gemm_tc<0, 0, 3, 1><<<gPV, 256, SMEMSZ>>>(ph, vh, nullptr, nullptr,
        nullptr, abh, SK, SK, NB * EE, NB * EE, SBATCH, EE, EE, 1.f);
    CVT(sa_ow, wh, nW1);
    gemm_tc<1, 0, 0, 0><<<gProj, 256, SMEMSZ>>>(abh, wh, sa_ob, x,
        x, nullptr, EE, EE, EE, EE, 0, 0, 0, 1.f);

    // ---------------- cross-attention ----------------
    ln_kernel<<<MTOK, 256>>>(x, ln2_g, ln2_b, hh);
    CVT(memory, mh, nM);
    CVT(ca_qw, wh, nW1);
    gemm_tc<1, 0, 3, 0><<<gProj, 256, SMEMSZ>>>(hh, wh, ca_b, nullptr,
        nullptr, qh, EE, EE, EE, EE, 0, 0, 0, scale);
    CVT(ca_kw, wh, nW1);
    gemm_tc<1, 0, 3, 0><<<gProj, 256, SMEMSZ>>>(mh, wh, ca_b + EE, nullptr,
        nullptr, kh, EE, EE, EE, EE, 0, 0, 0, 1.f);
    CVT(ca_vw, wh, nW1);
    gemm_tc<1, 0, 3, 0><<<gProj, 256, SMEMSZ>>>(mh, wh, ca_b + 2 * EE, nullptr,
        nullptr, vh, EE, EE, EE, EE, 0, 0, 0, 1.f);
    gemm_tc<1, 0, 0, 0><<<gScore, 256, SMEMSZ>>>(qh, kh, nullptr, nullptr,
        sb, nullptr, EE, NB * EE, NB * EE, SK, EE, EE, SBATCH, 1.f);
    softmax_kernel<<<NB * LQ, 256>>>(sb, nullptr, ph);
    gemm_tc<0, 0, 3, 0><<<gPV, 256, SMEMSZ>>>(ph, vh, nullptr, nullptr,
        nullptr, abh, SK, SK, NB * EE, NB * EE, SBATCH, EE, EE, 1.f);
    CVT(ca_ow, wh, nW1);
    gemm_tc<1, 0, 0, 0><<<gProj, 256, SMEMSZ>>>(abh, wh, ca_ob, x,
        x, nullptr, EE, EE, EE, EE, 0, 0, 0, 1.f);

    // ---------------- MLP ----------------
    ln_kernel<<<MTOK, 256>>>(x, ln3_g, ln3_b, hh);
    CVT(w1, wh, nFF);
    gemm_tc<1, 1, 3, 0><<<gFF1, 256, SMEMSZ>>>(hh, wh, b1, nullptr,
        nullptr, ffh, EE, EE, EE, FFD, 0, 0, 0, 1.f);
    CVT(w2, wh, nFF);
    gemm_tc<1, 0, 0, 0><<<gProj, 256, SMEMSZ>>>(ffh, wh, b2, x,
        x, nullptr, FFD, FFD, FFD, EE, 0, 0, 0, 1.f);
#undef CVT
}

// round 7
// speedup vs baseline: 11.4595x; 1.0322x over previous
#include <cuda_runtime.h>
#include <cuda_fp16.h>
#include <math.h>
#include <stdint.h>

#define LQ   2048
#define SK   2048
#define NB   4
#define EE   1024
#define FFD  4096
#define MTOK (LQ * NB)

typedef __half  f16;
typedef __half2 f162;

// ---------------------------------------------------------------------------
// Scratch (device globals)
// ---------------------------------------------------------------------------
__device__ f16 s_hh [(size_t)MTOK * EE];          // LN out
__device__ f16 s_qkv[(size_t)MTOK * 3 * EE];      // self q|k|v fused
__device__ f16 s_qh [(size_t)MTOK * EE];          // cross q
__device__ f16 s_kv [(size_t)MTOK * 2 * EE];      // cross k|v fused
__device__ f16 s_ph [(size_t)NB * LQ * SK];       // probs
__device__ f16 s_abh[(size_t)MTOK * EE];          // attn out
__device__ f16 s_ffh[(size_t)MTOK * FFD];         // MLP hidden
__device__ f16 s_mh [(size_t)MTOK * EE];          // memory fp16
__device__ f16 s_w3 [(size_t)3 * EE * EE];        // sa qkv weights
__device__ f16 s_wow[(size_t)EE * EE];            // sa out w
__device__ f16 s_cq [(size_t)EE * EE];            // ca q w
__device__ f16 s_ckv[(size_t)2 * EE * EE];        // ca kv weights
__device__ f16 s_cow[(size_t)EE * EE];            // ca out w
__device__ f16 s_w1 [(size_t)FFD * EE];
__device__ f16 s_w2 [(size_t)FFD * EE];
__device__ float g_s [(size_t)NB * LQ * SK];      // f32 scores

// ---------------------------------------------------------------------------
// Helpers
// ---------------------------------------------------------------------------
__device__ __forceinline__ float warpSum(float v) {
#pragma unroll
    for (int o = 16; o > 0; o >>= 1) v += __shfl_xor_sync(0xffffffffu, v, o);
    return v;
}
__device__ __forceinline__ float warpMax(float v) {
#pragma unroll
    for (int o = 16; o > 0; o >>= 1) v = fmaxf(v, __shfl_xor_sync(0xffffffffu, v, o));
    return v;
}
__device__ __forceinline__ float blockSum(float v, float* sh) {
    int lane = threadIdx.x & 31, wid = threadIdx.x >> 5;
    v = warpSum(v);
    if (lane == 0) sh[wid] = v;
    __syncthreads();
    float r = (lane < 8) ? sh[lane] : 0.f;
    r = warpSum(r);
    __syncthreads();
    return r;
}
__device__ __forceinline__ float blockMax(float v, float* sh) {
    int lane = threadIdx.x & 31, wid = threadIdx.x >> 5;
    v = warpMax(v);
    if (lane == 0) sh[wid] = v;
    __syncthreads();
    float r = (lane < 8) ? sh[lane] : -3.4e38f;
    r = warpMax(r);
    __syncthreads();
    return r;
}

// ---------------------------------------------------------------------------
// PTX wrappers (sm_80-class — compute_103-safe)
// ---------------------------------------------------------------------------
__device__ __forceinline__ void cpa16(uint32_t dst, const void* src) {
    asm volatile("cp.async.cg.shared.global [%0], [%1], 16;" :: "r"(dst), "l"(src));
}
#define CP_COMMIT() asm volatile("cp.async.commit_group;" ::: "memory")
#define CP_WAIT0()  asm volatile("cp.async.wait_group 0;" ::: "memory")
#define CP_WAIT1()  asm volatile("cp.async.wait_group 1;" ::: "memory")

__device__ __forceinline__ void ldsm4(uint32_t* r, uint32_t addr) {
    asm volatile("ldmatrix.sync.aligned.m8n8.x4.shared.b16 {%0,%1,%2,%3}, [%4];"
        : "=r"(r[0]), "=r"(r[1]), "=r"(r[2]), "=r"(r[3]) : "r"(addr));
}
__device__ __forceinline__ void ldsm2(uint32_t* r, uint32_t addr) {
    asm volatile("ldmatrix.sync.aligned.m8n8.x2.shared.b16 {%0,%1}, [%2];"
        : "=r"(r[0]), "=r"(r[1]) : "r"(addr));
}
__device__ __forceinline__ void ldsm2t(uint32_t* r, uint32_t addr) {
    asm volatile("ldmatrix.sync.aligned.m8n8.x2.trans.shared.b16 {%0,%1}, [%2];"
        : "=r"(r[0]), "=r"(r[1]) : "r"(addr));
}
__device__ __forceinline__ void mma_f16(float* d, const uint32_t* a, const uint32_t* b) {
    asm volatile(
        "mma.sync.aligned.m16n8k16.row.col.f32.f16.f16.f32 "
        "{%0,%1,%2,%3}, {%4,%5,%6,%7}, {%8,%9}, {%0,%1,%2,%3};\n"
        : "+f"(d[0]), "+f"(d[1]), "+f"(d[2]), "+f"(d[3])
        : "r"(a[0]), "r"(a[1]), "r"(a[2]), "r"(a[3]), "r"(b[0]), "r"(b[1]));
}

// ---------------------------------------------------------------------------
// f32 -> fp16 convert
// ---------------------------------------------------------------------------
__global__ void cvt_kernel(const float* __restrict__ x, f16* __restrict__ o,
                           long long n4) {
    long long i = blockIdx.x * (long long)blockDim.x + threadIdx.x;
    if (i >= n4) return;
    float4 v = ((const float4*)x)[i];
    ((f162*)o)[i * 2]     = __halves2half2(__float2half_rn(v.x), __float2half_rn(v.y));
    ((f162*)o)[i * 2 + 1] = __halves2half2(__float2half_rn(v.z), __float2half_rn(v.w));
}

// ---------------------------------------------------------------------------
// LayerNorm -> fp16
// ---------------------------------------------------------------------------
__global__ void ln_kernel(const float* __restrict__ x, const float* __restrict__ g,
                          const float* __restrict__ b, f16* __restrict__ oh) {
    __shared__ float sh[32];
    long long row = blockIdx.x;
    float4 v = ((const float4*)(x + row * EE))[threadIdx.x];
    float s  = v.x + v.y + v.z + v.w;
    float sq = v.x * v.x + v.y * v.y + v.z * v.z + v.w * v.w;
    s  = blockSum(s,  sh);
    sq = blockSum(sq, sh);
    float mean = s * (1.f / EE);
    float var  = sq * (1.f / EE) - mean * mean;
    float inv  = rsqrtf(var + 1e-5f);
    float4 gv = ((const float4*)g)[threadIdx.x];
    float4 bv = ((const float4*)b)[threadIdx.x];
    float o0 = (v.x - mean) * inv * gv.x + bv.x;
    float o1 = (v.y - mean) * inv * gv.y + bv.y;
    float o2 = (v.z - mean) * inv * gv.z + bv.z;
    float o3 = (v.w - mean) * inv * gv.w + bv.w;
    f162* ph = (f162*)(oh + row * EE);
    ph[threadIdx.x * 2]     = __halves2half2(__float2half_rn(o0), __float2half_rn(o1));
    ph[threadIdx.x * 2 + 1] = __halves2half2(__float2half_rn(o2), __float2half_rn(o3));
}

// ---------------------------------------------------------------------------
// Softmax over S=2048 -> fp16 probs; mask-select (skipped tiles never read)
// ---------------------------------------------------------------------------
__global__ void softmax_kernel(const float* __restrict__ s, const float* __restrict__ mask,
                               f16* __restrict__ oh) {
    __shared__ float sh[32];
    long long row = blockIdx.x;
    int l = (int)(row & (LQ - 1));
    const float4* sr = (const float4*)(s + row * (long long)SK);
    float4 va = sr[threadIdx.x];
    float4 vb = sr[threadIdx.x + 256];
    if (mask) {
        const float4* mr = (const float4*)(mask + (long long)l * SK);
        float4 ma = mr[threadIdx.x], mb = mr[threadIdx.x + 256];
        va.x = (ma.x < -1e8f) ? -3.0e38f : va.x;
        va.y = (ma.y < -1e8f) ? -3.0e38f : va.y;
        va.z = (ma.z < -1e8f) ? -3.0e38f : va.z;
        va.w = (ma.w < -1e8f) ? -3.0e38f : va.w;
        vb.x = (mb.x < -1e8f) ? -3.0e38f : vb.x;
        vb.y = (mb.y < -1e8f) ? -3.0e38f : vb.y;
        vb.z = (mb.z < -1e8f) ? -3.0e38f : vb.z;
        vb.w = (mb.w < -1e8f) ? -3.0e38f : vb.w;
    }
    float mx = fmaxf(fmaxf(fmaxf(va.x, va.y), fmaxf(va.z, va.w)),
                     fmaxf(fmaxf(vb.x, vb.y), fmaxf(vb.z, vb.w)));
    mx = blockMax(mx, sh);
    va.x = __expf(va.x - mx); va.y = __expf(va.y - mx);
    va.z = __expf(va.z - mx); va.w = __expf(va.w - mx);
    vb.x = __expf(vb.x - mx); vb.y = __expf(vb.y - mx);
    vb.z = __expf(vb.z - mx); vb.w = __expf(vb.w - mx);
    float sum = va.x + va.y + va.z + va.w + vb.x + vb.y + vb.z + vb.w;
    sum = blockSum(sum, sh);
    float inv = 1.f / sum;
    f162* ph = (f162*)(oh + row * (long long)SK);
    ph[threadIdx.x * 2] = __halves2half2(__float2half_rn(va.x * inv), __float2half_rn(va.y * inv));
    ph[threadIdx.x * 2 + 1] = __halves2half2(__float2half_rn(va.z * inv), __float2half_rn(va.w * inv));
    ph[(threadIdx.x + 256) * 2] = __halves2half2(__float2half_rn(vb.x * inv), __float2half_rn(vb.y * inv));
    ph[(threadIdx.x + 256) * 2 + 1] = __halves2half2(__float2half_rn(vb.z * inv), __float2half_rn(vb.w * inv));
}

// ---------------------------------------------------------------------------
// Tensor-core GEMM, single-term fp16: C = epi(A @ op(B)).
// 128x128 CTA tile, BK=32, 256 threads (2x4 warps), 64x32 warp tile.
// 3-stage cp.async pipeline, one __syncthreads per K-step, 2 CTA/SM.
// TRANSB=1: B [N,K] row-major. TRANSB=0: B [K,N].
// ACT: 0 none, 1 QuickGELU, 2 = scale (alpha) applied only to cols < EE (QKV).
// OUT: 0 = f32 (+res), 3 = fp16.
// CAUSAL: 0 none, 1 = K truncated at bm+128 (P@V), 2 = skip tiles bn>bm.
// ---------------------------------------------------------------------------
#define B_OFF  10240u
#define STAGE  20480u
#define SMEMSZ (3u * STAGE)

template <int TRANSB, int ACT, int OUT, int CAUSAL>
__global__ void __launch_bounds__(256, 2)
gemm_tc(const f16* __restrict__ Ah, const f16* __restrict__ Bh,
        const float* __restrict__ bias, const float* __restrict__ res,
        float* C, f16* Ch,
        int K, int lda, int ldb, int ldc,
        long long sA, long long sB, long long sC, float alpha) {
    const int bm = blockIdx.y * 128;
    const int bn = blockIdx.x * 128;
    if (CAUSAL == 2 && bn > bm) return;     // fully-masked score tile

    Ah += (long long)blockIdx.z * sA;
    Bh += (long long)blockIdx.z * sB;
    if (OUT == 0) { C  += (long long)blockIdx.z * sC; if (res) res += (long long)blockIdx.z * sC; }
    else          { Ch += (long long)blockIdx.z * sC; }

    extern __shared__ f16 smem[];
    const uint32_t sbase = (uint32_t)__cvta_generic_to_shared(smem);
    const int tid  = threadIdx.x;
    const int lane = tid & 31;
    const int warp = tid >> 5;
    const int wm = warp >> 2;   // 0..1
    const int wn = warp & 3;    // 0..3

    float acc[4][4][4];
#pragma unroll
    for (int i = 0; i < 4; i++)
#pragma unroll
        for (int j = 0; j < 4; j++)
#pragma unroll
            for (int q = 0; q < 4; q++) acc[i][j][q] = 0.f;

    auto load_stage = [&](int st, int k0) {
        uint32_t sb = sbase + (uint32_t)st * STAGE;
#pragma unroll
        for (int i = 0; i < 2; i++) {               // A: 128 rows x 4 16B chunks
            int c = tid + i * 256;
            int row = c >> 2, kc = c & 3;
            size_t off = (size_t)(bm + row) * lda + k0 + kc * 8;
            cpa16(sb + row * 80 + kc * 16, Ah + off);
        }
        if (TRANSB) {
#pragma unroll
            for (int i = 0; i < 2; i++) {           // B: 128 rows x 4 chunks
                int c = tid + i * 256;
                int row = c >> 2, kc = c & 3;
                size_t off = (size_t)(bn + row) * ldb + k0 + kc * 8;
                cpa16(sb + B_OFF + row * 80 + kc * 16, Bh + off);
            }
        } else {
#pragma unroll
            for (int i = 0; i < 2; i++) {           // B: 32 k-rows x 16 chunks
                int c = tid + i * 256;
                int row = c >> 4, nc = c & 15;
                size_t off = (size_t)(k0 + row) * ldb + bn + nc * 8;
                cpa16(sb + B_OFF + row * 272 + nc * 16, Bh + off);
            }
        }
        CP_COMMIT();
    };

    auto compute_stage = [&](int st) {
        uint32_t sA_ = sbase + (uint32_t)st * STAGE;
        uint32_t sB_ = sA_ + B_OFF;
#pragma unroll
        for (int ks = 0; ks < 2; ks++) {
            const int k16 = ks * 16;
            uint32_t ah[4][4], bh[4][2];
            const int arow = lane & 15;
            const int acol = k16 + (lane >> 4) * 8;
#pragma unroll
            for (int mt = 0; mt < 4; mt++) {
                uint32_t addr = sA_ + (uint32_t)((wm * 64 + mt * 16 + arow) * 80 + acol * 2);
                ldsm4(ah[mt], addr);
            }
            if (TRANSB) {
                const int brow = lane & 7;
                const int bk   = k16 + ((lane >> 3) & 1) * 8;
#pragma unroll
                for (int nt = 0; nt < 4; nt++) {
                    uint32_t addr = sB_ + (uint32_t)((wn * 32 + nt * 8 + brow) * 80 + bk * 2);
                    ldsm2(bh[nt], addr);
                }
            } else {
                const int brow = k16 + (lane & 15);
#pragma unroll
                for (int nt = 0; nt < 4; nt++) {
                    uint32_t addr = sB_ + (uint32_t)(brow * 272 + (wn * 32 + nt * 8) * 2);
                    ldsm2t(bh[nt], addr);
                }
            }
#pragma unroll
            for (int mt = 0; mt < 4; mt++)
#pragma unroll
                for (int nt = 0; nt < 4; nt++)
                    mma_f16(acc[mt][nt], ah[mt], bh[nt]);
        }
    };

    const int Kend = (CAUSAL == 1) ? min(K, bm + 128) : K;
    const int KT = Kend >> 5;
    load_stage(0, 0);
    if (KT > 1) load_stage(1, 32);
    for (int kt = 0; kt < KT; kt++) {
        if (kt + 1 < KT) CP_WAIT1(); else CP_WAIT0();
        __syncthreads();
        if (kt + 2 < KT) load_stage((kt + 2) % 3, (kt + 2) * 32);
        compute_stage(kt % 3);
    }

    // Epilogue
#pragma unroll
    for (int mt = 0; mt < 4; mt++) {
        const int r0 = bm + wm * 64 + mt * 16 + (lane >> 2);
#pragma unroll
        for (int nt = 0; nt < 4; nt++) {
            const int c = bn + wn * 32 + nt * 8 + (lane & 3) * 2;
            float bc0 = 0.f, bc1 = 0.f;
            if (bias) { bc0 = bias[c]; bc1 = bias[c + 1]; }
            const float af = (ACT == 2) ? ((c < EE) ? alpha : 1.f) : alpha;
#pragma unroll
            for (int h = 0; h < 2; h++) {
                float v0 = acc[mt][nt][h * 2 + 0] + bc0;
                float v1 = acc[mt][nt][h * 2 + 1] + bc1;
                v0 *= af; v1 *= af;
                if (ACT == 1) {
                    v0 = v0 / (1.f + __expf(-1.702f * v0));
                    v1 = v1 / (1.f + __expf(-1.702f * v1));
                }
                const size_t row = (size_t)(r0 + h * 8);
                if (OUT == 0) {
                    if (res) {
                        const float2 rv = *(const float2*)(res + row * ldc + c);
                        v0 += rv.x; v1 += rv.y;
                    }
                    *(float2*)(C + row * ldc + c) = make_float2(v0, v1);
                } else {
                    *(f162*)(Ch + row * ldc + c) =
                        __halves2half2(__float2half_rn(v0), __float2half_rn(v1));
                }
            }
        }
    }
}

// ---------------------------------------------------------------------------
// Host launcher
// ---------------------------------------------------------------------------
extern "C" void kernel_launch(void* const* d_in, const int* in_sizes, int n_in,
                              void* d_out, int out_size) {
    const float* tgt    = (const float*)d_in[0];
    const float* memory = (const float*)d_in[1];
    const float* mask   = (const float*)d_in[2];
    const float* sa_qw  = (const float*)d_in[3];
    const float* sa_kw  = (const float*)d_in[4];
    const float* sa_vw  = (const float*)d_in[5];
    const float* sa_b   = (const float*)d_in[6];
    const float* sa_ow  = (const float*)d_in[7];
    const float* sa_ob  = (const float*)d_in[8];
    const float* ca_qw  = (const float*)d_in[9];
    const float* ca_kw  = (const float*)d_in[10];
    const float* ca_vw  = (const float*)d_in[11];
    const float* ca_b   = (const float*)d_in[12];
    const float* ca_ow  = (const float*)d_in[13];
    const float* ca_ob  = (const float*)d_in[14];
    const float* ln1_g  = (const float*)d_in[15];
    const float* ln1_b  = (const float*)d_in[16];
    const float* ln2_g  = (const float*)d_in[17];
    const float* ln2_b  = (const float*)d_in[18];
    const float* ln3_g  = (const float*)d_in[19];
    const float* ln3_b  = (const float*)d_in[20];
    const float* w1     = (const float*)d_in[21];
    const float* b1     = (const float*)d_in[22];
    const float* w2     = (const float*)d_in[23];
    const float* b2     = (const float*)d_in[24];
    float* x = (float*)d_out;

    f16 *hh, *qkv, *qh, *kv, *ph, *abh, *ffh, *mh, *w3, *wow, *cq, *ckv, *cow, *wf1, *wf2;
    float* sb;
    cudaGetSymbolAddress((void**)&hh,  s_hh);
    cudaGetSymbolAddress((void**)&qkv, s_qkv);
    cudaGetSymbolAddress((void**)&qh,  s_qh);
    cudaGetSymbolAddress((void**)&kv,  s_kv);
    cudaGetSymbolAddress((void**)&ph,  s_ph);
    cudaGetSymbolAddress((void**)&abh, s_abh);
    cudaGetSymbolAddress((void**)&ffh, s_ffh);
    cudaGetSymbolAddress((void**)&mh,  s_mh);
    cudaGetSymbolAddress((void**)&w3,  s_w3);
    cudaGetSymbolAddress((void**)&wow, s_wow);
    cudaGetSymbolAddress((void**)&cq,  s_cq);
    cudaGetSymbolAddress((void**)&ckv, s_ckv);
    cudaGetSymbolAddress((void**)&cow, s_cow);
    cudaGetSymbolAddress((void**)&wf1, s_w1);
    cudaGetSymbolAddress((void**)&wf2, s_w2);
    cudaGetSymbolAddress((void**)&sb,  g_s);

    cudaFuncSetAttribute(gemm_tc<1, 2, 3, 0>, cudaFuncAttributeMaxDynamicSharedMemorySize, SMEMSZ);
    cudaFuncSetAttribute(gemm_tc<1, 0, 3, 0>, cudaFuncAttributeMaxDynamicSharedMemorySize, SMEMSZ);
    cudaFuncSetAttribute(gemm_tc<1, 0, 0, 0>, cudaFuncAttributeMaxDynamicSharedMemorySize, SMEMSZ);
    cudaFuncSetAttribute(gemm_tc<1, 0, 0, 2>, cudaFuncAttributeMaxDynamicSharedMemorySize, SMEMSZ);
    cudaFuncSetAttribute(gemm_tc<0, 0, 3, 0>, cudaFuncAttributeMaxDynamicSharedMemorySize, SMEMSZ);
    cudaFuncSetAttribute(gemm_tc<0, 0, 3, 1>, cudaFuncAttributeMaxDynamicSharedMemorySize, SMEMSZ);
    cudaFuncSetAttribute(gemm_tc<1, 1, 3, 0>, cudaFuncAttributeMaxDynamicSharedMemorySize, SMEMSZ);

    const float scale = 1.0f / 32.0f;
    const long long SBATCH = (long long)LQ * SK;
    const long long nW1 = (long long)EE * EE / 4;
    const long long nFF = (long long)FFD * EE / 4;
    const long long nM  = (long long)MTOK * EE / 4;

#define CVT(src, dst, n4) cvt_kernel<<<(unsigned)((n4) / 256), 256>>>(src, dst, n4)

    dim3 gQKV(3 * EE / 128, MTOK / 128);    // (24, 64)
    dim3 gKV(2 * EE / 128, MTOK / 128);     // (16, 64)
    dim3 gProj(EE / 128, MTOK / 128);       // (8, 64)
    dim3 gScore(SK / 128, LQ / 128, NB);    // (16, 16, 4)
    dim3 gPV(EE / 128, LQ / 128, NB);       // (8, 16, 4)
    dim3 gFF1(FFD / 128, MTOK / 128);       // (32, 64)

    // ---------------- self-attention ----------------
    // launches 1-5: ln + 4 cvts; launch 6 = fused QKV GEMM (ncu -s 5 captures it)
    ln_kernel<<<MTOK, 256>>>(tgt, ln1_g, ln1_b, hh);
    CVT(sa_qw, w3,                       nW1);
    CVT(sa_kw, w3 + (size_t)EE * EE,     nW1);
    CVT(sa_vw, w3 + (size_t)2 * EE * EE, nW1);
    CVT(sa_ow, wow,                      nW1);
    // qkv[MTOK, 3E] = hh @ W3^T + sa_b, q-cols scaled
    gemm_tc<1, 2, 3, 0><<<gQKV, 256, SMEMSZ>>>(hh, w3, sa_b, nullptr,
        nullptr, qkv, EE, EE, EE, 3 * EE, 0, 0, 0, scale);
    // scores: q = qkv(+0), k = qkv(+E); per-batch offset 3E, row stride NB*3E
    gemm_tc<1, 0, 0, 2><<<gScore, 256, SMEMSZ>>>(qkv, qkv + EE, nullptr, nullptr,
        sb, nullptr, EE, NB * 3 * EE, NB * 3 * EE, SK, 3 * EE, 3 * EE, SBATCH, 1.f);
    softmax_kernel<<<NB * LQ, 256>>>(sb, mask, ph);
    // P@V: v = qkv(+2E), [K,N] view with row stride NB*3E
    gemm_tc<0, 0, 3, 1><<<gPV, 256, SMEMSZ>>>(ph, qkv + 2 * EE, nullptr, nullptr,
        nullptr, abh, SK, SK, NB * 3 * EE, NB * EE, SBATCH, 3 * EE, EE, 1.f);
    // x = tgt + attn @ ow^T + ob   (no memcpy needed)
    gemm_tc<1, 0, 0, 0><<<gProj, 256, SMEMSZ>>>(abh, wow, sa_ob, tgt,
        x, nullptr, EE, EE, EE, EE, 0, 0, 0, 1.f);

    // ---------------- cross-attention ----------------
    CVT(memory, mh, nM);
    CVT(ca_qw, cq,                        nW1);
    CVT(ca_kw, ckv,                       nW1);
    CVT(ca_vw, ckv + (size_t)EE * EE,     nW1);
    CVT(ca_ow, cow,                       nW1);
    ln_kernel<<<MTOK, 256>>>(x, ln2_g, ln2_b, hh);
    gemm_tc<1, 0, 3, 0><<<gProj, 256, SMEMSZ>>>(hh, cq, ca_b, nullptr,
        nullptr, qh, EE, EE, EE, EE, 0, 0, 0, scale);
    // kv[MTOK, 2E] = mh @ CKV^T + ca_b[E..3E)
    gemm_tc<1, 0, 3, 0><<<gKV, 256, SMEMSZ>>>(mh, ckv, ca_b + EE, nullptr,
        nullptr, kv, EE, EE, EE, 2 * EE, 0, 0, 0, 1.f);
    gemm_tc<1, 0, 0, 0><<<gScore, 256, SMEMSZ>>>(qh, kv, nullptr, nullptr,
        sb, nullptr, EE, NB * EE, NB * 2 * EE, SK, EE, 2 * EE, SBATCH, 1.f);
    softmax_kernel<<<NB * LQ, 256>>>(sb, nullptr, ph);
    gemm_tc<0, 0, 3, 0><<<gPV, 256, SMEMSZ>>>(ph, kv + EE, nullptr, nullptr,
        nullptr, abh, SK, SK, NB * 2 * EE, NB * EE, SBATCH, 2 * EE, EE, 1.f);
    gemm_tc<1, 0, 0, 0><<<gProj, 256, SMEMSZ>>>(abh, cow, ca_ob, x,
        x, nullptr, EE, EE, EE, EE, 0, 0, 0, 1.f);

    // ---------------- MLP ----------------
    CVT(w1, wf1, nFF);
    CVT(w2, wf2, nFF);
    ln_kernel<<<MTOK, 256>>>(x, ln3_g, ln3_b, hh);
    gemm_tc<1, 1, 3, 0><<<gFF1, 256, SMEMSZ>>>(hh, wf1, b1, nullptr,
        nullptr, ffh, EE, EE, EE, FFD, 0, 0, 0, 1.f);
    gemm_tc<1, 0, 0, 0><<<gProj, 256, SMEMSZ>>>(ffh, wf2, b2, x,
        x, nullptr, FFD, FFD, FFD, EE, 0, 0, 0, 1.f);
#undef CVT
}